// round 1
// baseline (speedup 1.0000x reference)
#include <cuda_runtime.h>
#include <math.h>

// ---------------- problem dims (compile-time) ----------------
#define B_   4
#define L_   2048
#define DM_  1024
#define DS_  16
#define DC_  4
#define DI_  2048
#define N1_  4096              // 2*DI
#define M_   (B_ * L_)         // 8192
#define KSPLIT 8               // K-split for the small-N projection GEMM

// ---------------- scratch (module-load allocated, legal) ----------------
__device__ float g_xinner[(size_t)M_ * N1_];   // 134 MB
__device__ float g_xconv [(size_t)M_ * DI_];   // 67 MB
__device__ float g_yskip [(size_t)M_ * DI_];   // 67 MB
__device__ float g_part  [KSPLIT * M_ * 48];   // partial dots (delta|B|C)
__device__ float g_rspart[KSPLIT * M_];        // partial row sums
__device__ float g_G[M_ * DS_];
__device__ float g_U[M_ * DS_];
__device__ float g_Cs[M_ * DS_];
__device__ float g_y[M_];

// ---------------- big GEMM: C[M,N] = A[M,K] @ B[N,K]^T (both K-major) ------
// 128x128 tile, k-tile 8, 256 threads, 8x8 per thread, fp32 FFMA.
__global__ __launch_bounds__(256) void gemm_nt_kernel(
    const float* __restrict__ A, const float* __restrict__ B,
    float* __restrict__ C, int M, int N, int K)
{
    __shared__ float As[8][128];
    __shared__ float Bs[8][128];

    const int tid = threadIdx.x;
    const int tx  = tid & 15;      // 0..15 -> N fragment
    const int ty  = tid >> 4;      // 0..15 -> M fragment
    const int m0  = blockIdx.y * 128;
    const int n0  = blockIdx.x * 128;

    const int lrow = tid >> 1;          // 0..127
    const int lcol = (tid & 1) * 4;     // 0 or 4
    const float* Ag = A + (size_t)(m0 + lrow) * K + lcol;
    const float* Bg = B + (size_t)(n0 + lrow) * K + lcol;

    float acc[8][8];
    #pragma unroll
    for (int i = 0; i < 8; i++)
        #pragma unroll
        for (int j = 0; j < 8; j++) acc[i][j] = 0.f;

    for (int k0 = 0; k0 < K; k0 += 8) {
        float4 av = *(const float4*)(Ag + k0);
        float4 bv = *(const float4*)(Bg + k0);
        __syncthreads();                 // prev tile fully consumed
        As[lcol + 0][lrow] = av.x;
        As[lcol + 1][lrow] = av.y;
        As[lcol + 2][lrow] = av.z;
        As[lcol + 3][lrow] = av.w;
        Bs[lcol + 0][lrow] = bv.x;
        Bs[lcol + 1][lrow] = bv.y;
        Bs[lcol + 2][lrow] = bv.z;
        Bs[lcol + 3][lrow] = bv.w;
        __syncthreads();

        #pragma unroll
        for (int k = 0; k < 8; k++) {
            float4 a0 = *(const float4*)&As[k][ty * 8];
            float4 a1 = *(const float4*)&As[k][ty * 8 + 4];
            float4 b0 = *(const float4*)&Bs[k][tx * 8];
            float4 b1 = *(const float4*)&Bs[k][tx * 8 + 4];
            float a[8] = {a0.x, a0.y, a0.z, a0.w, a1.x, a1.y, a1.z, a1.w};
            float b[8] = {b0.x, b0.y, b0.z, b0.w, b1.x, b1.y, b1.z, b1.w};
            #pragma unroll
            for (int i = 0; i < 8; i++)
                #pragma unroll
                for (int j = 0; j < 8; j++)
                    acc[i][j] = fmaf(a[i], b[j], acc[i][j]);
        }
    }

    #pragma unroll
    for (int i = 0; i < 8; i++) {
        float4 v0 = make_float4(acc[i][0], acc[i][1], acc[i][2], acc[i][3]);
        float4 v1 = make_float4(acc[i][4], acc[i][5], acc[i][6], acc[i][7]);
        float* cp = C + (size_t)(m0 + ty * 8 + i) * N + n0 + tx * 8;
        *(float4*)(cp)     = v0;
        *(float4*)(cp + 4) = v1;
    }
}

// ---------------- causal depthwise conv (DC=4) + silu ----------------
__global__ __launch_bounds__(256) void conv_silu_kernel(
    const float* __restrict__ cw, const float* __restrict__ cb)
{
    int gid = blockIdx.x * blockDim.x + threadIdx.x;
    if (gid >= M_ * (DI_ / 4)) return;
    int iq = gid & (DI_ / 4 - 1);   // 0..511
    int r  = gid >> 9;              // 0..8191
    int i  = iq * 4;
    int b  = r >> 11;
    int l  = r & (L_ - 1);

    float4 bias = *(const float4*)(cb + i);
    float acc[4] = {bias.x, bias.y, bias.z, bias.w};

    float w[4][4];
    #pragma unroll
    for (int j = 0; j < 4; j++) {
        float4 t = *(const float4*)(cw + (i + j) * DC_);
        w[j][0] = t.x; w[j][1] = t.y; w[j][2] = t.z; w[j][3] = t.w;
    }
    #pragma unroll
    for (int k = 0; k < DC_; k++) {
        int ls = l + k - (DC_ - 1);
        if (ls >= 0) {
            float4 xv = *(const float4*)(g_xinner + (size_t)(b * L_ + ls) * N1_ + i);
            acc[0] = fmaf(xv.x, w[0][k], acc[0]);
            acc[1] = fmaf(xv.y, w[1][k], acc[1]);
            acc[2] = fmaf(xv.z, w[2][k], acc[2]);
            acc[3] = fmaf(xv.w, w[3][k], acc[3]);
        }
    }
    float4 o;
    o.x = acc[0] / (1.f + expf(-acc[0]));
    o.y = acc[1] / (1.f + expf(-acc[1]));
    o.z = acc[2] / (1.f + expf(-acc[2]));
    o.w = acc[3] / (1.f + expf(-acc[3]));
    *(float4*)(g_xconv + (size_t)r * DI_ + i) = o;
}

// ---------------- small-N GEMM: dots[8192,48] = x_conv @ [dw;Bw;Cw]^T -------
// grid (64 M-tiles, 8 K-chunks). Also accumulates per-row sums for xavg.
#define KT2 16
__global__ __launch_bounds__(256) void dbc_kernel(
    const float* __restrict__ dw, const float* __restrict__ bw,
    const float* __restrict__ cw)
{
    __shared__ float As[KT2][128];
    __shared__ float Ws[KT2][48];

    const int tid = threadIdx.x;
    const int m0  = blockIdx.x * 128;
    const int kbase = blockIdx.y * (DI_ / KSPLIT);   // 256-wide K chunk
    const int r  = tid >> 1;
    const int cg = tid & 1;

    float acc[24];
    #pragma unroll
    for (int j = 0; j < 24; j++) acc[j] = 0.f;
    float rowsum = 0.f;

    const int arow = tid >> 1;
    const int acol = (tid & 1) * 8;

    for (int kt = 0; kt < DI_ / KSPLIT; kt += KT2) {
        int k0 = kbase + kt;
        __syncthreads();
        {
            const float* src = g_xconv + (size_t)(m0 + arow) * DI_ + k0 + acol;
            float4 v0 = *(const float4*)(src);
            float4 v1 = *(const float4*)(src + 4);
            As[acol + 0][arow] = v0.x; As[acol + 1][arow] = v0.y;
            As[acol + 2][arow] = v0.z; As[acol + 3][arow] = v0.w;
            As[acol + 4][arow] = v1.x; As[acol + 5][arow] = v1.y;
            As[acol + 6][arow] = v1.z; As[acol + 7][arow] = v1.w;
            if (tid < 192) {
                int wrow = tid >> 2;
                int wcol = (tid & 3) * 4;
                const float* wp = (wrow < 16) ? dw + wrow * DI_
                               : (wrow < 32) ? bw + (wrow - 16) * DI_
                                             : cw + (wrow - 32) * DI_;
                float4 wv = *(const float4*)(wp + k0 + wcol);
                Ws[wcol + 0][wrow] = wv.x; Ws[wcol + 1][wrow] = wv.y;
                Ws[wcol + 2][wrow] = wv.z; Ws[wcol + 3][wrow] = wv.w;
            }
        }
        __syncthreads();
        #pragma unroll
        for (int k = 0; k < KT2; k++) {
            float a = As[k][r];
            rowsum += a;
            #pragma unroll
            for (int j = 0; j < 24; j++)
                acc[j] = fmaf(a, Ws[k][cg * 24 + j], acc[j]);
        }
    }

    float* pb = g_part + (size_t)blockIdx.y * M_ * 48 + (size_t)(m0 + r) * 48 + cg * 24;
    #pragma unroll
    for (int j = 0; j < 24; j++) pb[j] = acc[j];
    if (cg == 0) g_rspart[blockIdx.y * M_ + m0 + r] = rowsum;
}

// ---------------- reduce partials, compute G=exp(dA), U=d*B*xavg, Cs --------
__global__ __launch_bounds__(256) void gu_kernel(
    const float* __restrict__ A_log, const float* __restrict__ delta_b)
{
    int gid = blockIdx.x * blockDim.x + threadIdx.x;
    if (gid >= M_ * DS_) return;
    int r = gid >> 4;
    int s = gid & 15;
    float dd = 0.f, db = 0.f, dc = 0.f, rs = 0.f;
    #pragma unroll
    for (int p = 0; p < KSPLIT; p++) {
        const float* pp = g_part + (size_t)p * M_ * 48 + (size_t)r * 48;
        dd += pp[s];
        db += pp[16 + s];
        dc += pp[32 + s];
        rs += g_rspart[p * M_ + r];
    }
    float z = dd + delta_b[s];
    float delta = (z > 20.f) ? z : log1pf(expf(z));
    float Aval = -expf(A_log[s]);
    g_G[gid]  = expf(delta * Aval);
    g_U[gid]  = delta * db * (rs * (1.f / (float)DI_));
    g_Cs[gid] = dc;
}

// ---------------- sequential scan: h = G*h + U ; y = sum(h*C) ----------------
__global__ void scan_kernel()
{
    int b = blockIdx.x;              // 4 blocks, 1 warp each
    int lane = threadIdx.x;
    int s = lane & 15;
    bool active = lane < 16;
    float h = 0.f;
    const float* Gp = g_G  + (size_t)b * L_ * DS_;
    const float* Up = g_U  + (size_t)b * L_ * DS_;
    const float* Cp = g_Cs + (size_t)b * L_ * DS_;
    #pragma unroll 4
    for (int l = 0; l < L_; l++) {
        int idx = l * DS_ + s;
        float gv = Gp[idx];
        float uv = Up[idx];
        float cv = Cp[idx];
        h = fmaf(gv, h, uv);
        float p = active ? h * cv : 0.f;
        #pragma unroll
        for (int o = 8; o >= 1; o >>= 1)
            p += __shfl_xor_sync(0xffffffffu, p, o);
        if (lane == 0) g_y[b * L_ + l] = p;
    }
}

// ---------------- y_skip = y*silu(gate) + x_conv*D ----------------
__global__ __launch_bounds__(256) void yskip_kernel(const float* __restrict__ Dp)
{
    int gid = blockIdx.x * blockDim.x + threadIdx.x;
    if (gid >= M_ * (DI_ / 4)) return;
    int iq = gid & (DI_ / 4 - 1);
    int r  = gid >> 9;
    int i  = iq * 4;
    float4 gt = *(const float4*)(g_xinner + (size_t)r * N1_ + DI_ + i);
    float4 xc = *(const float4*)(g_xconv + (size_t)r * DI_ + i);
    float4 dv = *(const float4*)(Dp + i);
    float yv = g_y[r];
    float4 o;
    o.x = fmaf(yv, gt.x / (1.f + expf(-gt.x)), xc.x * dv.x);
    o.y = fmaf(yv, gt.y / (1.f + expf(-gt.y)), xc.y * dv.y);
    o.z = fmaf(yv, gt.z / (1.f + expf(-gt.z)), xc.z * dv.z);
    o.w = fmaf(yv, gt.w / (1.f + expf(-gt.w)), xc.w * dv.w);
    *(float4*)(g_yskip + (size_t)r * DI_ + i) = o;
}

// ---------------- launch ----------------
extern "C" void kernel_launch(void* const* d_in, const int* in_sizes, int n_in,
                              void* d_out, int out_size)
{
    const float* x          = (const float*)d_in[0];
    const float* in_proj_w  = (const float*)d_in[1];
    const float* conv_w     = (const float*)d_in[2];
    const float* conv_b     = (const float*)d_in[3];
    const float* A_log      = (const float*)d_in[4];
    const float* Dp         = (const float*)d_in[5];
    const float* delta_w    = (const float*)d_in[6];
    const float* delta_b    = (const float*)d_in[7];
    const float* B_w        = (const float*)d_in[8];
    const float* C_w        = (const float*)d_in[9];
    const float* out_proj_w = (const float*)d_in[10];
    float* out = (float*)d_out;

    float *p_xinner = nullptr, *p_yskip = nullptr;
    cudaGetSymbolAddress((void**)&p_xinner, g_xinner);
    cudaGetSymbolAddress((void**)&p_yskip,  g_yskip);

    // 1) x_inner = x @ in_proj_w^T   [8192,4096]
    gemm_nt_kernel<<<dim3(N1_ / 128, M_ / 128), 256>>>(
        x, in_proj_w, p_xinner, M_, N1_, DM_);

    // 2) causal conv + silu -> x_conv
    conv_silu_kernel<<<(M_ * (DI_ / 4) + 255) / 256, 256>>>(conv_w, conv_b);

    // 3) delta/B/C dots + row sums (K-split partials)
    dbc_kernel<<<dim3(M_ / 128, KSPLIT), 256>>>(delta_w, B_w, C_w);

    // 4) reduce partials, compute scan coefficients
    gu_kernel<<<(M_ * DS_ + 255) / 256, 256>>>(A_log, delta_b);

    // 5) sequential scan (coefficients precomputed -> pure FMA chain)
    scan_kernel<<<B_, 32>>>();

    // 6) gate + skip fuse
    yskip_kernel<<<(M_ * (DI_ / 4) + 255) / 256, 256>>>(Dp);

    // 7) out = y_skip @ out_proj_w^T   [8192,1024]
    gemm_nt_kernel<<<dim3(DM_ / 128, M_ / 128), 256>>>(
        p_yskip, out_proj_w, out, M_, DM_, DI_);
}

// round 3
// speedup vs baseline: 1.9170x; 1.9170x over previous
#include <cuda_runtime.h>
#include <cuda_bf16.h>
#include <math.h>
#include <stdint.h>

// ---------------- problem dims ----------------
#define B_   4
#define L_   2048
#define DM_  1024
#define DS_  16
#define DC_  4
#define DI_  2048
#define N1_  4096              // 2*DI
#define M_   (B_ * L_)         // 8192
#define KSPLIT 8

// ---------------- scratch (__device__ globals, no allocation) ----------------
__device__ float g_xinner[(size_t)M_ * N1_];
__device__ float g_xconv [(size_t)M_ * DI_];
__device__ float g_part  [KSPLIT * M_ * 48];
__device__ float g_rspart[KSPLIT * M_];
__device__ float g_G[M_ * DS_];
__device__ float g_U[M_ * DS_];
__device__ float g_Cs[M_ * DS_];
__device__ float g_y[M_];
__device__ __nv_bfloat16 g_xh [(size_t)M_  * DM_];
__device__ __nv_bfloat16 g_xl [(size_t)M_  * DM_];
__device__ __nv_bfloat16 g_w1h[(size_t)N1_ * DM_];
__device__ __nv_bfloat16 g_w1l[(size_t)N1_ * DM_];
__device__ __nv_bfloat16 g_woh[(size_t)DM_ * DI_];
__device__ __nv_bfloat16 g_wol[(size_t)DM_ * DI_];
__device__ __nv_bfloat16 g_ysh[(size_t)M_  * DI_];
__device__ __nv_bfloat16 g_ysl[(size_t)M_  * DI_];

// ---------------- helpers ----------------
__device__ __forceinline__ uint32_t smem_u32(const void* p) {
    uint32_t a;
    asm("{ .reg .u64 t; cvta.to.shared.u64 t, %1; cvt.u32.u64 %0, t; }" : "=r"(a) : "l"(p));
    return a;
}
__device__ __forceinline__ void cp16(uint32_t dst, const void* src) {
    asm volatile("cp.async.cg.shared.global [%0], [%1], 16;" :: "r"(dst), "l"(src));
}
__device__ __forceinline__ void cp_commit() {
    asm volatile("cp.async.commit_group;" ::: "memory");
}
__device__ __forceinline__ void cp_wait0() {
    asm volatile("cp.async.wait_group 0;" ::: "memory");
}
__device__ __forceinline__ void cp_wait1() {
    asm volatile("cp.async.wait_group 1;" ::: "memory");
}
__device__ __forceinline__ void ldm_x4(uint32_t* r, uint32_t addr) {
    asm volatile("ldmatrix.sync.aligned.m8n8.x4.shared.b16 {%0,%1,%2,%3}, [%4];"
        : "=r"(r[0]), "=r"(r[1]), "=r"(r[2]), "=r"(r[3]) : "r"(addr));
}
__device__ __forceinline__ void ldm_x2(uint32_t* r, uint32_t addr) {
    asm volatile("ldmatrix.sync.aligned.m8n8.x2.shared.b16 {%0,%1}, [%2];"
        : "=r"(r[0]), "=r"(r[1]) : "r"(addr));
}
__device__ __forceinline__ void mma_bf16(float* c, const uint32_t* a, const uint32_t* b) {
    asm volatile(
        "mma.sync.aligned.m16n8k16.row.col.f32.bf16.bf16.f32 "
        "{%0,%1,%2,%3}, {%4,%5,%6,%7}, {%8,%9}, {%0,%1,%2,%3};"
        : "+f"(c[0]), "+f"(c[1]), "+f"(c[2]), "+f"(c[3])
        : "r"(a[0]), "r"(a[1]), "r"(a[2]), "r"(a[3]), "r"(b[0]), "r"(b[1]));
}

// ---------------- HMMA split-bf16 GEMM: C[M,N] = A[M,K] @ W[N,K]^T ----------
// Block 128x128, k-tile 32, 8 warps (2m x 4n), warp tile 64x32.
// SMEM rows padded to 40 bf16 (80B) -> conflict-free ldmatrix.
#define BM 128
#define BN 128
#define BK 32
#define LDS_ROW 40                       // bf16 elems per smem row (32 + 8 pad)
#define TILE_B (128 * LDS_ROW * 2)       // 10240 bytes per 128x32 tile
#define STAGE_B (4 * TILE_B)             // Ah, Al, Wh, Wl
#define SMEM_TOTAL (2 * STAGE_B)         // 81920

__device__ __forceinline__ void stage_load(uint32_t sbase,
    const __nv_bfloat16* __restrict__ Ah, const __nv_bfloat16* __restrict__ Al,
    const __nv_bfloat16* __restrict__ Wh, const __nv_bfloat16* __restrict__ Wl,
    int k0, int K, int tid)
{
    const __nv_bfloat16* srcs[4] = {Ah, Al, Wh, Wl};
    #pragma unroll
    for (int a = 0; a < 4; a++) {
        #pragma unroll
        for (int i = 0; i < 2; i++) {
            int idx = i * 256 + tid;        // 0..511
            int row = idx >> 2;
            int c8  = (idx & 3) * 8;
            const void* g = srcs[a] + (size_t)row * K + k0 + c8;
            uint32_t s = sbase + a * TILE_B + row * (LDS_ROW * 2) + c8 * 2;
            cp16(s, g);
        }
    }
}

__global__ __launch_bounds__(256, 1) void gemm_tc(
    const __nv_bfloat16* __restrict__ Ah, const __nv_bfloat16* __restrict__ Al,
    const __nv_bfloat16* __restrict__ Wh, const __nv_bfloat16* __restrict__ Wl,
    float* __restrict__ C, int M, int N, int K)
{
    extern __shared__ char smem[];
    uint32_t sb = smem_u32(smem);
    const int tid = threadIdx.x, wid = tid >> 5, lane = tid & 31;
    const int wm = wid >> 2, wn = wid & 3;       // warp 64x32 tile
    const int m0 = blockIdx.y * BM, n0 = blockIdx.x * BN;

    const __nv_bfloat16* Ahp = Ah + (size_t)m0 * K;
    const __nv_bfloat16* Alp = Al + (size_t)m0 * K;
    const __nv_bfloat16* Whp = Wh + (size_t)n0 * K;
    const __nv_bfloat16* Wlp = Wl + (size_t)n0 * K;

    float acc[4][4][4];
    #pragma unroll
    for (int i = 0; i < 4; i++)
        #pragma unroll
        for (int j = 0; j < 4; j++)
            #pragma unroll
            for (int q = 0; q < 4; q++) acc[i][j][q] = 0.f;

    const int T = K / BK;
    stage_load(sb, Ahp, Alp, Whp, Wlp, 0, K, tid);
    cp_commit();

    // ldmatrix lane addressing (fixed per thread)
    const int l15 = lane & 15;
    const int a_row_off = l15;                       // + 16B sel below
    const int a_khalf = (lane >> 4) & 1;             // 0: k0-7, 1: k8-15
    const int b_nloc = lane & 7;
    const int b_khalf = (l15 >> 3) & 1;

    for (int t = 0; t < T; t++) {
        uint32_t cur = sb + (t & 1) * STAGE_B;
        if (t + 1 < T) {
            stage_load(sb + ((t + 1) & 1) * STAGE_B, Ahp, Alp, Whp, Wlp,
                       (t + 1) * BK, K, tid);
            cp_commit();
            cp_wait1();
        } else {
            cp_wait0();
        }
        __syncthreads();

        #pragma unroll
        for (int kk = 0; kk < 2; kk++) {
            uint32_t ah[4][4], al[4][4], whf[4][2], wlf[4][2];
            #pragma unroll
            for (int mi = 0; mi < 4; mi++) {
                int row = wm * 64 + mi * 16 + a_row_off;
                uint32_t addr = cur + row * (LDS_ROW * 2) + kk * 32 + a_khalf * 16;
                ldm_x4(ah[mi], addr + 0 * TILE_B);
                ldm_x4(al[mi], addr + 1 * TILE_B);
            }
            #pragma unroll
            for (int ni = 0; ni < 4; ni++) {
                int row = wn * 32 + ni * 8 + b_nloc;
                uint32_t addr = cur + row * (LDS_ROW * 2) + kk * 32 + b_khalf * 16;
                ldm_x2(whf[ni], addr + 2 * TILE_B);
                ldm_x2(wlf[ni], addr + 3 * TILE_B);
            }
            #pragma unroll
            for (int mi = 0; mi < 4; mi++)
                #pragma unroll
                for (int ni = 0; ni < 4; ni++) {
                    mma_bf16(acc[mi][ni], ah[mi], whf[ni]);
                    mma_bf16(acc[mi][ni], ah[mi], wlf[ni]);
                    mma_bf16(acc[mi][ni], al[mi], whf[ni]);
                }
        }
        __syncthreads();
    }

    // epilogue: fragment rows = groupid, cols = tid*2
    const int g = lane >> 2, tq = lane & 3;
    #pragma unroll
    for (int mi = 0; mi < 4; mi++) {
        #pragma unroll
        for (int ni = 0; ni < 4; ni++) {
            int row = m0 + wm * 64 + mi * 16 + g;
            int col = n0 + wn * 32 + ni * 8 + tq * 2;
            *(float2*)(C + (size_t)row * N + col) =
                make_float2(acc[mi][ni][0], acc[mi][ni][1]);
            *(float2*)(C + (size_t)(row + 8) * N + col) =
                make_float2(acc[mi][ni][2], acc[mi][ni][3]);
        }
    }
}

// ---------------- fp32 -> (hi, lo) bf16 split ----------------
__global__ __launch_bounds__(256) void split_kernel(const float* __restrict__ src,
    __nv_bfloat16* __restrict__ hi, __nv_bfloat16* __restrict__ lo, int n4)
{
    int i = blockIdx.x * blockDim.x + threadIdx.x;
    if (i >= n4) return;
    float4 v = ((const float4*)src)[i];
    float f[4] = {v.x, v.y, v.z, v.w};
    uint32_t ph[2] = {0, 0}, pl[2] = {0, 0};
    #pragma unroll
    for (int j = 0; j < 4; j++) {
        __nv_bfloat16 h = __float2bfloat16(f[j]);
        __nv_bfloat16 l = __float2bfloat16(f[j] - __bfloat162float(h));
        uint32_t hu = *reinterpret_cast<unsigned short*>(&h);
        uint32_t lu = *reinterpret_cast<unsigned short*>(&l);
        ph[j >> 1] |= hu << ((j & 1) * 16);
        pl[j >> 1] |= lu << ((j & 1) * 16);
    }
    ((uint2*)hi)[i] = make_uint2(ph[0], ph[1]);
    ((uint2*)lo)[i] = make_uint2(pl[0], pl[1]);
}

// ---------------- causal depthwise conv (DC=4) + silu ----------------
__global__ __launch_bounds__(256) void conv_silu_kernel(
    const float* __restrict__ cw, const float* __restrict__ cb)
{
    int gid = blockIdx.x * blockDim.x + threadIdx.x;
    if (gid >= M_ * (DI_ / 4)) return;
    int iq = gid & (DI_ / 4 - 1);
    int r  = gid >> 9;
    int i  = iq * 4;
    int b  = r >> 11;
    int l  = r & (L_ - 1);

    float4 bias = *(const float4*)(cb + i);
    float acc[4] = {bias.x, bias.y, bias.z, bias.w};
    float w[4][4];
    #pragma unroll
    for (int j = 0; j < 4; j++) {
        float4 t = *(const float4*)(cw + (i + j) * DC_);
        w[j][0] = t.x; w[j][1] = t.y; w[j][2] = t.z; w[j][3] = t.w;
    }
    #pragma unroll
    for (int k = 0; k < DC_; k++) {
        int ls = l + k - (DC_ - 1);
        if (ls >= 0) {
            float4 xv = *(const float4*)(g_xinner + (size_t)(b * L_ + ls) * N1_ + i);
            acc[0] = fmaf(xv.x, w[0][k], acc[0]);
            acc[1] = fmaf(xv.y, w[1][k], acc[1]);
            acc[2] = fmaf(xv.z, w[2][k], acc[2]);
            acc[3] = fmaf(xv.w, w[3][k], acc[3]);
        }
    }
    float4 o;
    o.x = acc[0] / (1.f + expf(-acc[0]));
    o.y = acc[1] / (1.f + expf(-acc[1]));
    o.z = acc[2] / (1.f + expf(-acc[2]));
    o.w = acc[3] / (1.f + expf(-acc[3]));
    *(float4*)(g_xconv + (size_t)r * DI_ + i) = o;
}

// ---------------- small-N GEMM: dots[8192,48] + row sums ----------------
#define KT2 16
__global__ __launch_bounds__(256) void dbc_kernel(
    const float* __restrict__ dw, const float* __restrict__ bw,
    const float* __restrict__ cw)
{
    __shared__ float As[KT2][128];
    __shared__ float Ws[KT2][48];
    const int tid = threadIdx.x;
    const int m0  = blockIdx.x * 128;
    const int kbase = blockIdx.y * (DI_ / KSPLIT);
    const int r  = tid >> 1;
    const int cg = tid & 1;

    float acc[24];
    #pragma unroll
    for (int j = 0; j < 24; j++) acc[j] = 0.f;
    float rowsum = 0.f;
    const int arow = tid >> 1;
    const int acol = (tid & 1) * 8;

    for (int kt = 0; kt < DI_ / KSPLIT; kt += KT2) {
        int k0 = kbase + kt;
        __syncthreads();
        {
            const float* src = g_xconv + (size_t)(m0 + arow) * DI_ + k0 + acol;
            float4 v0 = *(const float4*)(src);
            float4 v1 = *(const float4*)(src + 4);
            As[acol + 0][arow] = v0.x; As[acol + 1][arow] = v0.y;
            As[acol + 2][arow] = v0.z; As[acol + 3][arow] = v0.w;
            As[acol + 4][arow] = v1.x; As[acol + 5][arow] = v1.y;
            As[acol + 6][arow] = v1.z; As[acol + 7][arow] = v1.w;
            if (tid < 192) {
                int wrow = tid >> 2;
                int wcol = (tid & 3) * 4;
                const float* wp = (wrow < 16) ? dw + wrow * DI_
                               : (wrow < 32) ? bw + (wrow - 16) * DI_
                                             : cw + (wrow - 32) * DI_;
                float4 wv = *(const float4*)(wp + k0 + wcol);
                Ws[wcol + 0][wrow] = wv.x; Ws[wcol + 1][wrow] = wv.y;
                Ws[wcol + 2][wrow] = wv.z; Ws[wcol + 3][wrow] = wv.w;
            }
        }
        __syncthreads();
        #pragma unroll
        for (int k = 0; k < KT2; k++) {
            float a = As[k][r];
            rowsum += a;
            #pragma unroll
            for (int j = 0; j < 24; j++)
                acc[j] = fmaf(a, Ws[k][cg * 24 + j], acc[j]);
        }
    }
    float* pb = g_part + (size_t)blockIdx.y * M_ * 48 + (size_t)(m0 + r) * 48 + cg * 24;
    #pragma unroll
    for (int j = 0; j < 24; j++) pb[j] = acc[j];
    if (cg == 0) g_rspart[blockIdx.y * M_ + m0 + r] = rowsum;
}

// ---------------- reduce partials -> scan coefficients ----------------
__global__ __launch_bounds__(256) void gu_kernel(
    const float* __restrict__ A_log, const float* __restrict__ delta_b)
{
    int gid = blockIdx.x * blockDim.x + threadIdx.x;
    if (gid >= M_ * DS_) return;
    int r = gid >> 4;
    int s = gid & 15;
    float dd = 0.f, db = 0.f, dc = 0.f, rs = 0.f;
    #pragma unroll
    for (int p = 0; p < KSPLIT; p++) {
        const float* pp = g_part + (size_t)p * M_ * 48 + (size_t)r * 48;
        dd += pp[s];
        db += pp[16 + s];
        dc += pp[32 + s];
        rs += g_rspart[p * M_ + r];
    }
    float z = dd + delta_b[s];
    float delta = (z > 20.f) ? z : log1pf(expf(z));
    float Aval = -expf(A_log[s]);
    g_G[gid]  = expf(delta * Aval);
    g_U[gid]  = delta * db * (rs * (1.f / (float)DI_));
    g_Cs[gid] = dc;
}

// ---------------- sequential scan ----------------
__global__ void scan_kernel()
{
    int b = blockIdx.x;
    int lane = threadIdx.x;
    int s = lane & 15;
    bool active = lane < 16;
    float h = 0.f;
    const float* Gp = g_G  + (size_t)b * L_ * DS_;
    const float* Up = g_U  + (size_t)b * L_ * DS_;
    const float* Cp = g_Cs + (size_t)b * L_ * DS_;
    #pragma unroll 4
    for (int l = 0; l < L_; l++) {
        int idx = l * DS_ + s;
        float gv = Gp[idx];
        float uv = Up[idx];
        float cv = Cp[idx];
        h = fmaf(gv, h, uv);
        float p = active ? h * cv : 0.f;
        #pragma unroll
        for (int o = 8; o >= 1; o >>= 1)
            p += __shfl_xor_sync(0xffffffffu, p, o);
        if (lane == 0) g_y[b * L_ + l] = p;
    }
}

// ---------------- y_skip = y*silu(gate) + x_conv*D  -> bf16 hi/lo ----------
__global__ __launch_bounds__(256) void yskip_kernel(const float* __restrict__ Dp)
{
    int gid = blockIdx.x * blockDim.x + threadIdx.x;
    if (gid >= M_ * (DI_ / 4)) return;
    int iq = gid & (DI_ / 4 - 1);
    int r  = gid >> 9;
    int i  = iq * 4;
    float4 gt = *(const float4*)(g_xinner + (size_t)r * N1_ + DI_ + i);
    float4 xc = *(const float4*)(g_xconv + (size_t)r * DI_ + i);
    float4 dv = *(const float4*)(Dp + i);
    float yv = g_y[r];
    float f[4];
    f[0] = fmaf(yv, gt.x / (1.f + expf(-gt.x)), xc.x * dv.x);
    f[1] = fmaf(yv, gt.y / (1.f + expf(-gt.y)), xc.y * dv.y);
    f[2] = fmaf(yv, gt.z / (1.f + expf(-gt.z)), xc.z * dv.z);
    f[3] = fmaf(yv, gt.w / (1.f + expf(-gt.w)), xc.w * dv.w);
    uint32_t ph[2] = {0, 0}, pl[2] = {0, 0};
    #pragma unroll
    for (int j = 0; j < 4; j++) {
        __nv_bfloat16 h = __float2bfloat16(f[j]);
        __nv_bfloat16 l = __float2bfloat16(f[j] - __bfloat162float(h));
        uint32_t hu = *reinterpret_cast<unsigned short*>(&h);
        uint32_t lu = *reinterpret_cast<unsigned short*>(&l);
        ph[j >> 1] |= hu << ((j & 1) * 16);
        pl[j >> 1] |= lu << ((j & 1) * 16);
    }
    size_t o = (size_t)r * (DI_ / 4) + iq;
    ((uint2*)g_ysh)[o] = make_uint2(ph[0], ph[1]);
    ((uint2*)g_ysl)[o] = make_uint2(pl[0], pl[1]);
}

// ---------------- launch ----------------
extern "C" void kernel_launch(void* const* d_in, const int* in_sizes, int n_in,
                              void* d_out, int out_size)
{
    const float* x          = (const float*)d_in[0];
    const float* in_proj_w  = (const float*)d_in[1];
    const float* conv_w     = (const float*)d_in[2];
    const float* conv_b     = (const float*)d_in[3];
    const float* A_log      = (const float*)d_in[4];
    const float* Dp         = (const float*)d_in[5];
    const float* delta_w    = (const float*)d_in[6];
    const float* delta_b    = (const float*)d_in[7];
    const float* B_w        = (const float*)d_in[8];
    const float* C_w        = (const float*)d_in[9];
    const float* out_proj_w = (const float*)d_in[10];
    float* out = (float*)d_out;

    float *p_xinner = nullptr;
    __nv_bfloat16 *p_xh, *p_xl, *p_w1h, *p_w1l, *p_woh, *p_wol, *p_ysh, *p_ysl;
    cudaGetSymbolAddress((void**)&p_xinner, g_xinner);
    cudaGetSymbolAddress((void**)&p_xh,  g_xh);
    cudaGetSymbolAddress((void**)&p_xl,  g_xl);
    cudaGetSymbolAddress((void**)&p_w1h, g_w1h);
    cudaGetSymbolAddress((void**)&p_w1l, g_w1l);
    cudaGetSymbolAddress((void**)&p_woh, g_woh);
    cudaGetSymbolAddress((void**)&p_wol, g_wol);
    cudaGetSymbolAddress((void**)&p_ysh, g_ysh);
    cudaGetSymbolAddress((void**)&p_ysl, g_ysl);

    cudaFuncSetAttribute(gemm_tc, cudaFuncAttributeMaxDynamicSharedMemorySize, SMEM_TOTAL);

    // 0) split inputs to hi/lo bf16
    split_kernel<<<(M_ * DM_ / 4 + 255) / 256, 256>>>(x, p_xh, p_xl, M_ * DM_ / 4);
    split_kernel<<<(N1_ * DM_ / 4 + 255) / 256, 256>>>(in_proj_w, p_w1h, p_w1l, N1_ * DM_ / 4);
    split_kernel<<<(DM_ * DI_ / 4 + 255) / 256, 256>>>(out_proj_w, p_woh, p_wol, DM_ * DI_ / 4);

    // 1) x_inner = x @ in_proj_w^T  [8192,4096]  (HMMA split-bf16)
    gemm_tc<<<dim3(N1_ / BN, M_ / BM), 256, SMEM_TOTAL>>>(
        p_xh, p_xl, p_w1h, p_w1l, p_xinner, M_, N1_, DM_);

    // 2) causal conv + silu
    conv_silu_kernel<<<(M_ * (DI_ / 4) + 255) / 256, 256>>>(conv_w, conv_b);

    // 3) delta/B/C dots + row sums
    dbc_kernel<<<dim3(M_ / 128, KSPLIT), 256>>>(delta_w, B_w, C_w);

    // 4) scan coefficients
    gu_kernel<<<(M_ * DS_ + 255) / 256, 256>>>(A_log, delta_b);

    // 5) sequential scan
    scan_kernel<<<B_, 32>>>();

    // 6) gate + skip fuse -> bf16 hi/lo
    yskip_kernel<<<(M_ * (DI_ / 4) + 255) / 256, 256>>>(Dp);

    // 7) out = y_skip @ out_proj_w^T  [8192,1024]  (HMMA split-bf16)
    gemm_tc<<<dim3(DM_ / BN, M_ / BM), 256, SMEM_TOTAL>>>(
        p_ysh, p_ysl, p_woh, p_wol, out, M_, DM_, DI_);
}

// round 4
// speedup vs baseline: 2.8254x; 1.4739x over previous
#include <cuda_runtime.h>
#include <cuda_bf16.h>
#include <math.h>
#include <stdint.h>

// ---------------- problem dims ----------------
#define B_   4
#define L_   2048
#define DM_  1024
#define DS_  16
#define DC_  4
#define DI_  2048
#define N1_  4096              // 2*DI
#define M_   (B_ * L_)         // 8192
#define KSPLIT 8

// ---------------- scratch (__device__ globals, no allocation) ----------------
__device__ float g_xinner[(size_t)M_ * N1_];
__device__ float g_xconv [(size_t)M_ * DI_];
__device__ float g_part  [KSPLIT * M_ * 48];
__device__ float g_rspart[KSPLIT * M_];
__device__ float g_G [M_ * DS_];   // s-major: [s][b*L+l]
__device__ float g_U [M_ * DS_];
__device__ float g_Cs[M_ * DS_];
__device__ float g_hc[M_ * DS_];   // h*C, s-major
__device__ float g_y[M_];
__device__ __nv_bfloat16 g_xh [(size_t)M_  * DM_];
__device__ __nv_bfloat16 g_xl [(size_t)M_  * DM_];
__device__ __nv_bfloat16 g_w1h[(size_t)N1_ * DM_];
__device__ __nv_bfloat16 g_w1l[(size_t)N1_ * DM_];
__device__ __nv_bfloat16 g_woh[(size_t)DM_ * DI_];
__device__ __nv_bfloat16 g_wol[(size_t)DM_ * DI_];
__device__ __nv_bfloat16 g_ysh[(size_t)M_  * DI_];
__device__ __nv_bfloat16 g_ysl[(size_t)M_  * DI_];

// ---------------- helpers ----------------
__device__ __forceinline__ uint32_t smem_u32(const void* p) {
    uint32_t a;
    asm("{ .reg .u64 t; cvta.to.shared.u64 t, %1; cvt.u32.u64 %0, t; }" : "=r"(a) : "l"(p));
    return a;
}
__device__ __forceinline__ void cp16(uint32_t dst, const void* src) {
    asm volatile("cp.async.cg.shared.global [%0], [%1], 16;" :: "r"(dst), "l"(src));
}
__device__ __forceinline__ void cp_commit() {
    asm volatile("cp.async.commit_group;" ::: "memory");
}
__device__ __forceinline__ void cp_wait1() {
    asm volatile("cp.async.wait_group 1;" ::: "memory");
}
__device__ __forceinline__ void ldm_x4(uint32_t* r, uint32_t addr) {
    asm volatile("ldmatrix.sync.aligned.m8n8.x4.shared.b16 {%0,%1,%2,%3}, [%4];"
        : "=r"(r[0]), "=r"(r[1]), "=r"(r[2]), "=r"(r[3]) : "r"(addr));
}
__device__ __forceinline__ void mma_bf16(float* c, const uint32_t* a, const uint32_t* b) {
    asm volatile(
        "mma.sync.aligned.m16n8k16.row.col.f32.bf16.bf16.f32 "
        "{%0,%1,%2,%3}, {%4,%5,%6,%7}, {%8,%9}, {%0,%1,%2,%3};"
        : "+f"(c[0]), "+f"(c[1]), "+f"(c[2]), "+f"(c[3])
        : "r"(a[0]), "r"(a[1]), "r"(a[2]), "r"(a[3]), "r"(b[0]), "r"(b[1]));
}

// ---------------- HMMA split-bf16 GEMM: C[M,N] = A[M,K] @ W[N,K]^T ----------
// Block 128x128, k-tile 32, 8 warps (2m x 4n), warp tile 64x32.
// 3-stage cp.async pipeline, ONE __syncthreads per k-tile.
#define BM 128
#define BN 128
#define BK 32
#define LDS_ROW 40                       // bf16 elems per smem row (32 + 8 pad)
#define TILE_B (128 * LDS_ROW * 2)       // 10240 bytes per 128x32 tile
#define STAGE_B (4 * TILE_B)             // Ah, Al, Wh, Wl
#define STAGES 3
#define SMEM_TOTAL (STAGES * STAGE_B)    // 122880

__device__ __forceinline__ void stage_load(uint32_t sbase,
    const __nv_bfloat16* __restrict__ Ah, const __nv_bfloat16* __restrict__ Al,
    const __nv_bfloat16* __restrict__ Wh, const __nv_bfloat16* __restrict__ Wl,
    int k0, int K, int tid)
{
    const __nv_bfloat16* srcs[4] = {Ah, Al, Wh, Wl};
    #pragma unroll
    for (int a = 0; a < 4; a++) {
        #pragma unroll
        for (int i = 0; i < 2; i++) {
            int idx = i * 256 + tid;        // 0..511
            int row = idx >> 2;
            int c8  = (idx & 3) * 8;
            const void* g = srcs[a] + (size_t)row * K + k0 + c8;
            uint32_t s = sbase + a * TILE_B + row * (LDS_ROW * 2) + c8 * 2;
            cp16(s, g);
        }
    }
}

__global__ __launch_bounds__(256, 1) void gemm_tc(
    const __nv_bfloat16* __restrict__ Ah, const __nv_bfloat16* __restrict__ Al,
    const __nv_bfloat16* __restrict__ Wh, const __nv_bfloat16* __restrict__ Wl,
    float* __restrict__ C, int M, int N, int K)
{
    extern __shared__ char smem[];
    uint32_t sb = smem_u32(smem);
    const int tid = threadIdx.x, wid = tid >> 5, lane = tid & 31;
    const int wm = wid >> 2, wn = wid & 3;       // warp 64x32 tile
    const int m0 = blockIdx.y * BM, n0 = blockIdx.x * BN;

    const __nv_bfloat16* Ahp = Ah + (size_t)m0 * K;
    const __nv_bfloat16* Alp = Al + (size_t)m0 * K;
    const __nv_bfloat16* Whp = Wh + (size_t)n0 * K;
    const __nv_bfloat16* Wlp = Wl + (size_t)n0 * K;

    float acc[4][4][4];
    #pragma unroll
    for (int i = 0; i < 4; i++)
        #pragma unroll
        for (int j = 0; j < 4; j++)
            #pragma unroll
            for (int q = 0; q < 4; q++) acc[i][j][q] = 0.f;

    const int T = K / BK;
    stage_load(sb + 0 * STAGE_B, Ahp, Alp, Whp, Wlp, 0, K, tid);
    cp_commit();
    stage_load(sb + 1 * STAGE_B, Ahp, Alp, Whp, Wlp, BK, K, tid);
    cp_commit();

    // ldmatrix lane addressing
    const int l15 = lane & 15;
    const int a_khalf = (lane >> 4) & 1;
    // B x4: grp 0/1 -> n-sub 0 klo/khi, grp 2/3 -> n-sub 1 klo/khi
    const int b_grp = lane >> 3, b_r = lane & 7;
    const int b_row_off = ((b_grp >> 1) << 3) + b_r;
    const int b_kb = (b_grp & 1) * 16;

    for (int t = 0; t < T; t++) {
        cp_wait1();                    // stage t landed (FIFO; <=1 outstanding)
        __syncthreads();               // all warps done with stage t-1 slot
        if (t + 2 < T)
            stage_load(sb + ((t + 2) % STAGES) * STAGE_B, Ahp, Alp, Whp, Wlp,
                       (t + 2) * BK, K, tid);
        cp_commit();                   // uniform commit keeps group count exact

        uint32_t cur = sb + (t % STAGES) * STAGE_B;
        #pragma unroll
        for (int kk = 0; kk < 2; kk++) {
            uint32_t ah[4][4], al[4][4], whf[2][4], wlf[2][4];
            #pragma unroll
            for (int mi = 0; mi < 4; mi++) {
                int row = wm * 64 + mi * 16 + l15;
                uint32_t addr = cur + row * (LDS_ROW * 2) + kk * 32 + a_khalf * 16;
                ldm_x4(ah[mi], addr + 0 * TILE_B);
                ldm_x4(al[mi], addr + 1 * TILE_B);
            }
            #pragma unroll
            for (int n2 = 0; n2 < 2; n2++) {
                int row = wn * 32 + n2 * 16 + b_row_off;
                uint32_t addr = cur + row * (LDS_ROW * 2) + kk * 32 + b_kb;
                ldm_x4(whf[n2], addr + 2 * TILE_B);
                ldm_x4(wlf[n2], addr + 3 * TILE_B);
            }
            #pragma unroll
            for (int mi = 0; mi < 4; mi++)
                #pragma unroll
                for (int ni = 0; ni < 4; ni++) {
                    const uint32_t* bh = &whf[ni >> 1][(ni & 1) * 2];
                    const uint32_t* bl = &wlf[ni >> 1][(ni & 1) * 2];
                    mma_bf16(acc[mi][ni], ah[mi], bh);
                    mma_bf16(acc[mi][ni], ah[mi], bl);
                    mma_bf16(acc[mi][ni], al[mi], bh);
                }
        }
    }

    const int g = lane >> 2, tq = lane & 3;
    #pragma unroll
    for (int mi = 0; mi < 4; mi++) {
        #pragma unroll
        for (int ni = 0; ni < 4; ni++) {
            int row = m0 + wm * 64 + mi * 16 + g;
            int col = n0 + wn * 32 + ni * 8 + tq * 2;
            *(float2*)(C + (size_t)row * N + col) =
                make_float2(acc[mi][ni][0], acc[mi][ni][1]);
            *(float2*)(C + (size_t)(row + 8) * N + col) =
                make_float2(acc[mi][ni][2], acc[mi][ni][3]);
        }
    }
}

// ---------------- fp32 -> (hi, lo) bf16 split ----------------
__global__ __launch_bounds__(256) void split_kernel(const float* __restrict__ src,
    __nv_bfloat16* __restrict__ hi, __nv_bfloat16* __restrict__ lo, int n4)
{
    int i = blockIdx.x * blockDim.x + threadIdx.x;
    if (i >= n4) return;
    float4 v = ((const float4*)src)[i];
    float f[4] = {v.x, v.y, v.z, v.w};
    uint32_t ph[2] = {0, 0}, pl[2] = {0, 0};
    #pragma unroll
    for (int j = 0; j < 4; j++) {
        __nv_bfloat16 h = __float2bfloat16(f[j]);
        __nv_bfloat16 l = __float2bfloat16(f[j] - __bfloat162float(h));
        uint32_t hu = *reinterpret_cast<unsigned short*>(&h);
        uint32_t lu = *reinterpret_cast<unsigned short*>(&l);
        ph[j >> 1] |= hu << ((j & 1) * 16);
        pl[j >> 1] |= lu << ((j & 1) * 16);
    }
    ((uint2*)hi)[i] = make_uint2(ph[0], ph[1]);
    ((uint2*)lo)[i] = make_uint2(pl[0], pl[1]);
}

// ---------------- causal depthwise conv (DC=4) + silu ----------------
__global__ __launch_bounds__(256) void conv_silu_kernel(
    const float* __restrict__ cw, const float* __restrict__ cb)
{
    int gid = blockIdx.x * blockDim.x + threadIdx.x;
    if (gid >= M_ * (DI_ / 4)) return;
    int iq = gid & (DI_ / 4 - 1);
    int r  = gid >> 9;
    int i  = iq * 4;
    int b  = r >> 11;
    int l  = r & (L_ - 1);

    float4 bias = *(const float4*)(cb + i);
    float acc[4] = {bias.x, bias.y, bias.z, bias.w};
    float w[4][4];
    #pragma unroll
    for (int j = 0; j < 4; j++) {
        float4 t = *(const float4*)(cw + (i + j) * DC_);
        w[j][0] = t.x; w[j][1] = t.y; w[j][2] = t.z; w[j][3] = t.w;
    }
    #pragma unroll
    for (int k = 0; k < DC_; k++) {
        int ls = l + k - (DC_ - 1);
        if (ls >= 0) {
            float4 xv = *(const float4*)(g_xinner + (size_t)(b * L_ + ls) * N1_ + i);
            acc[0] = fmaf(xv.x, w[0][k], acc[0]);
            acc[1] = fmaf(xv.y, w[1][k], acc[1]);
            acc[2] = fmaf(xv.z, w[2][k], acc[2]);
            acc[3] = fmaf(xv.w, w[3][k], acc[3]);
        }
    }
    float4 o;
    o.x = acc[0] / (1.f + expf(-acc[0]));
    o.y = acc[1] / (1.f + expf(-acc[1]));
    o.z = acc[2] / (1.f + expf(-acc[2]));
    o.w = acc[3] / (1.f + expf(-acc[3]));
    *(float4*)(g_xconv + (size_t)r * DI_ + i) = o;
}

// ---------------- small-N GEMM: dots[8192,48] + row sums ----------------
#define KT2 16
__global__ __launch_bounds__(256) void dbc_kernel(
    const float* __restrict__ dw, const float* __restrict__ bw,
    const float* __restrict__ cw)
{
    __shared__ float As[KT2][128];
    __shared__ float Ws[KT2][48];
    const int tid = threadIdx.x;
    const int m0  = blockIdx.x * 128;
    const int kbase = blockIdx.y * (DI_ / KSPLIT);
    const int r  = tid >> 1;
    const int cg = tid & 1;

    float acc[24];
    #pragma unroll
    for (int j = 0; j < 24; j++) acc[j] = 0.f;
    float rowsum = 0.f;
    const int arow = tid >> 1;
    const int acol = (tid & 1) * 8;

    for (int kt = 0; kt < DI_ / KSPLIT; kt += KT2) {
        int k0 = kbase + kt;
        __syncthreads();
        {
            const float* src = g_xconv + (size_t)(m0 + arow) * DI_ + k0 + acol;
            float4 v0 = *(const float4*)(src);
            float4 v1 = *(const float4*)(src + 4);
            As[acol + 0][arow] = v0.x; As[acol + 1][arow] = v0.y;
            As[acol + 2][arow] = v0.z; As[acol + 3][arow] = v0.w;
            As[acol + 4][arow] = v1.x; As[acol + 5][arow] = v1.y;
            As[acol + 6][arow] = v1.z; As[acol + 7][arow] = v1.w;
            if (tid < 192) {
                int wrow = tid >> 2;
                int wcol = (tid & 3) * 4;
                const float* wp = (wrow < 16) ? dw + wrow * DI_
                               : (wrow < 32) ? bw + (wrow - 16) * DI_
                                             : cw + (wrow - 32) * DI_;
                float4 wv = *(const float4*)(wp + k0 + wcol);
                Ws[wcol + 0][wrow] = wv.x; Ws[wcol + 1][wrow] = wv.y;
                Ws[wcol + 2][wrow] = wv.z; Ws[wcol + 3][wrow] = wv.w;
            }
        }
        __syncthreads();
        #pragma unroll
        for (int k = 0; k < KT2; k++) {
            float a = As[k][r];
            rowsum += a;
            #pragma unroll
            for (int j = 0; j < 24; j++)
                acc[j] = fmaf(a, Ws[k][cg * 24 + j], acc[j]);
        }
    }
    float* pb = g_part + (size_t)blockIdx.y * M_ * 48 + (size_t)(m0 + r) * 48 + cg * 24;
    #pragma unroll
    for (int j = 0; j < 24; j++) pb[j] = acc[j];
    if (cg == 0) g_rspart[blockIdx.y * M_ + m0 + r] = rowsum;
}

// ---------------- reduce partials -> scan coefficients (s-major out) --------
__global__ __launch_bounds__(256) void gu_kernel(
    const float* __restrict__ A_log, const float* __restrict__ delta_b)
{
    int gid = blockIdx.x * blockDim.x + threadIdx.x;
    if (gid >= M_ * DS_) return;
    int s = gid >> 13;              // gid / M_
    int r = gid & (M_ - 1);
    float dd = 0.f, db = 0.f, dc = 0.f, rs = 0.f;
    #pragma unroll
    for (int p = 0; p < KSPLIT; p++) {
        const float* pp = g_part + (size_t)p * M_ * 48 + (size_t)r * 48;
        dd += pp[s];
        db += pp[16 + s];
        dc += pp[32 + s];
        rs += g_rspart[p * M_ + r];
    }
    float z = dd + delta_b[s];
    float delta = (z > 20.f) ? z : log1pf(expf(z));
    float Aval = -expf(A_log[s]);
    size_t o = (size_t)s * M_ + r;
    g_G[o]  = expf(delta * Aval);
    g_U[o]  = delta * db * (rs * (1.f / (float)DI_));
    g_Cs[o] = dc;
}

// ---------------- parallel scan: one block per (b,s), 64 threads ------------
// chunk-local compose -> Hillis-Steele over 64 chunks -> replay, write h*C
__global__ __launch_bounds__(64) void scan2_kernel()
{
    __shared__ float sG[L_], sU[L_], sC[L_];
    __shared__ float sA[64], sB[64];
    const int b = blockIdx.x >> 4, s = blockIdx.x & 15;
    const int tid = threadIdx.x;
    const size_t base = (size_t)s * M_ + (size_t)b * L_;

    for (int i = tid; i < L_ / 4; i += 64) {
        ((float4*)sG)[i] = *(const float4*)(g_G  + base + i * 4);
        ((float4*)sU)[i] = *(const float4*)(g_U  + base + i * 4);
        ((float4*)sC)[i] = *(const float4*)(g_Cs + base + i * 4);
    }
    __syncthreads();

    const int CH = L_ / 64;   // 32
    const int l0 = tid * CH;
    float A = 1.f, U = 0.f;
    #pragma unroll
    for (int i = 0; i < CH; i++) {
        float gv = sG[l0 + i];
        A *= gv;
        U = fmaf(gv, U, sU[l0 + i]);
    }
    sA[tid] = A; sB[tid] = U;
    __syncthreads();

    #pragma unroll
    for (int d = 1; d < 64; d <<= 1) {
        float a2 = sA[tid], u2 = sB[tid];
        float a1 = 1.f, u1 = 0.f;
        if (tid >= d) { a1 = sA[tid - d]; u1 = sB[tid - d]; }
        __syncthreads();
        sA[tid] = a2 * a1;
        sB[tid] = fmaf(a2, u1, u2);
        __syncthreads();
    }

    float h = (tid == 0) ? 0.f : sB[tid - 1];
    #pragma unroll
    for (int i = 0; i < CH; i++) {
        h = fmaf(sG[l0 + i], h, sU[l0 + i]);
        sU[l0 + i] = h * sC[l0 + i];
    }
    __syncthreads();
    for (int i = tid; i < L_ / 4; i += 64)
        *(float4*)(g_hc + base + i * 4) = ((float4*)sU)[i];
}

// ---------------- y[r] = sum_s hc[s][r] ----------------
__global__ __launch_bounds__(256) void ysum_kernel()
{
    int r = blockIdx.x * blockDim.x + threadIdx.x;
    if (r >= M_) return;
    float acc = 0.f;
    #pragma unroll
    for (int s = 0; s < DS_; s++)
        acc += g_hc[(size_t)s * M_ + r];
    g_y[r] = acc;
}

// ---------------- y_skip = y*silu(gate) + x_conv*D  -> bf16 hi/lo ----------
__global__ __launch_bounds__(256) void yskip_kernel(const float* __restrict__ Dp)
{
    int gid = blockIdx.x * blockDim.x + threadIdx.x;
    if (gid >= M_ * (DI_ / 4)) return;
    int iq = gid & (DI_ / 4 - 1);
    int r  = gid >> 9;
    int i  = iq * 4;
    float4 gt = *(const float4*)(g_xinner + (size_t)r * N1_ + DI_ + i);
    float4 xc = *(const float4*)(g_xconv + (size_t)r * DI_ + i);
    float4 dv = *(const float4*)(Dp + i);
    float yv = g_y[r];
    float f[4];
    f[0] = fmaf(yv, gt.x / (1.f + expf(-gt.x)), xc.x * dv.x);
    f[1] = fmaf(yv, gt.y / (1.f + expf(-gt.y)), xc.y * dv.y);
    f[2] = fmaf(yv, gt.z / (1.f + expf(-gt.z)), xc.z * dv.z);
    f[3] = fmaf(yv, gt.w / (1.f + expf(-gt.w)), xc.w * dv.w);
    uint32_t ph[2] = {0, 0}, pl[2] = {0, 0};
    #pragma unroll
    for (int j = 0; j < 4; j++) {
        __nv_bfloat16 h = __float2bfloat16(f[j]);
        __nv_bfloat16 l = __float2bfloat16(f[j] - __bfloat162float(h));
        uint32_t hu = *reinterpret_cast<unsigned short*>(&h);
        uint32_t lu = *reinterpret_cast<unsigned short*>(&l);
        ph[j >> 1] |= hu << ((j & 1) * 16);
        pl[j >> 1] |= lu << ((j & 1) * 16);
    }
    size_t o = (size_t)r * (DI_ / 4) + iq;
    ((uint2*)g_ysh)[o] = make_uint2(ph[0], ph[1]);
    ((uint2*)g_ysl)[o] = make_uint2(pl[0], pl[1]);
}

// ---------------- launch ----------------
extern "C" void kernel_launch(void* const* d_in, const int* in_sizes, int n_in,
                              void* d_out, int out_size)
{
    const float* x          = (const float*)d_in[0];
    const float* in_proj_w  = (const float*)d_in[1];
    const float* conv_w     = (const float*)d_in[2];
    const float* conv_b     = (const float*)d_in[3];
    const float* A_log      = (const float*)d_in[4];
    const float* Dp         = (const float*)d_in[5];
    const float* delta_w    = (const float*)d_in[6];
    const float* delta_b    = (const float*)d_in[7];
    const float* B_w        = (const float*)d_in[8];
    const float* C_w        = (const float*)d_in[9];
    const float* out_proj_w = (const float*)d_in[10];
    float* out = (float*)d_out;

    float *p_xinner = nullptr;
    __nv_bfloat16 *p_xh, *p_xl, *p_w1h, *p_w1l, *p_woh, *p_wol, *p_ysh, *p_ysl;
    cudaGetSymbolAddress((void**)&p_xinner, g_xinner);
    cudaGetSymbolAddress((void**)&p_xh,  g_xh);
    cudaGetSymbolAddress((void**)&p_xl,  g_xl);
    cudaGetSymbolAddress((void**)&p_w1h, g_w1h);
    cudaGetSymbolAddress((void**)&p_w1l, g_w1l);
    cudaGetSymbolAddress((void**)&p_woh, g_woh);
    cudaGetSymbolAddress((void**)&p_wol, g_wol);
    cudaGetSymbolAddress((void**)&p_ysh, g_ysh);
    cudaGetSymbolAddress((void**)&p_ysl, g_ysl);

    cudaFuncSetAttribute(gemm_tc, cudaFuncAttributeMaxDynamicSharedMemorySize, SMEM_TOTAL);

    // 0) split inputs to hi/lo bf16
    split_kernel<<<(M_ * DM_ / 4 + 255) / 256, 256>>>(x, p_xh, p_xl, M_ * DM_ / 4);
    split_kernel<<<(N1_ * DM_ / 4 + 255) / 256, 256>>>(in_proj_w, p_w1h, p_w1l, N1_ * DM_ / 4);
    split_kernel<<<(DM_ * DI_ / 4 + 255) / 256, 256>>>(out_proj_w, p_woh, p_wol, DM_ * DI_ / 4);

    // 1) x_inner = x @ in_proj_w^T  [8192,4096]  (HMMA split-bf16)
    gemm_tc<<<dim3(N1_ / BN, M_ / BM), 256, SMEM_TOTAL>>>(
        p_xh, p_xl, p_w1h, p_w1l, p_xinner, M_, N1_, DM_);

    // 2) causal conv + silu
    conv_silu_kernel<<<(M_ * (DI_ / 4) + 255) / 256, 256>>>(conv_w, conv_b);

    // 3) delta/B/C dots + row sums
    dbc_kernel<<<dim3(M_ / 128, KSPLIT), 256>>>(delta_w, B_w, C_w);

    // 4) scan coefficients (s-major)
    gu_kernel<<<(M_ * DS_ + 255) / 256, 256>>>(A_log, delta_b);

    // 5) parallel scan + reduce over states
    scan2_kernel<<<B_ * DS_, 64>>>();
    ysum_kernel<<<(M_ + 255) / 256, 256>>>();

    // 6) gate + skip fuse -> bf16 hi/lo
    yskip_kernel<<<(M_ * (DI_ / 4) + 255) / 256, 256>>>(Dp);

    // 7) out = y_skip @ out_proj_w^T  [8192,1024]  (HMMA split-bf16)
    gemm_tc<<<dim3(DM_ / BN, M_ / BM), 256, SMEM_TOTAL>>>(
        p_ysh, p_ysl, p_woh, p_wol, out, M_, DM_, DI_);
}

// round 5
// speedup vs baseline: 4.0189x; 1.4224x over previous
#include <cuda_runtime.h>
#include <cuda_fp16.h>
#include <math.h>
#include <stdint.h>

// ---------------- problem dims ----------------
#define B_   4
#define L_   2048
#define DM_  1024
#define DS_  16
#define DC_  4
#define DI_  2048
#define N1_  4096              // 2*DI
#define M_   (B_ * L_)         // 8192
#define KSPLIT 8

// ---------------- scratch (__device__ globals, no allocation) ----------------
__device__ float g_xinner[(size_t)M_ * N1_];
__device__ float g_xconv [(size_t)M_ * DI_];
__device__ float g_part  [KSPLIT * M_ * 48];
__device__ float g_rspart[KSPLIT * M_];
__device__ float g_G [M_ * DS_];   // s-major: [s][b*L+l]
__device__ float g_U [M_ * DS_];
__device__ float g_Cs[M_ * DS_];
__device__ float g_hc[M_ * DS_];   // h*C, s-major
__device__ float g_y[M_];
__device__ __half g_xh [(size_t)M_  * DM_];
__device__ __half g_xl [(size_t)M_  * DM_];
__device__ __half g_w1 [(size_t)N1_ * DM_];
__device__ __half g_wo [(size_t)DM_ * DI_];
__device__ __half g_ysh[(size_t)M_  * DI_];
__device__ __half g_ysl[(size_t)M_  * DI_];

// ---------------- helpers ----------------
__device__ __forceinline__ uint32_t smem_u32(const void* p) {
    uint32_t a;
    asm("{ .reg .u64 t; cvta.to.shared.u64 t, %1; cvt.u32.u64 %0, t; }" : "=r"(a) : "l"(p));
    return a;
}
__device__ __forceinline__ void cp16(uint32_t dst, const void* src) {
    asm volatile("cp.async.cg.shared.global [%0], [%1], 16;" :: "r"(dst), "l"(src));
}
__device__ __forceinline__ void cp_commit() {
    asm volatile("cp.async.commit_group;" ::: "memory");
}
__device__ __forceinline__ void cp_wait1() {
    asm volatile("cp.async.wait_group 1;" ::: "memory");
}
__device__ __forceinline__ void ldm_x4(uint32_t* r, uint32_t addr) {
    asm volatile("ldmatrix.sync.aligned.m8n8.x4.shared.b16 {%0,%1,%2,%3}, [%4];"
        : "=r"(r[0]), "=r"(r[1]), "=r"(r[2]), "=r"(r[3]) : "r"(addr));
}
__device__ __forceinline__ void mma_fp16(float* c, const uint32_t* a, const uint32_t* b) {
    asm volatile(
        "mma.sync.aligned.m16n8k16.row.col.f32.f16.f16.f32 "
        "{%0,%1,%2,%3}, {%4,%5,%6,%7}, {%8,%9}, {%0,%1,%2,%3};"
        : "+f"(c[0]), "+f"(c[1]), "+f"(c[2]), "+f"(c[3])
        : "r"(a[0]), "r"(a[1]), "r"(a[2]), "r"(a[3]), "r"(b[0]), "r"(b[1]));
}

// ---------------- HMMA fp16 GEMM: C[M,N] = (Ah+Al)[M,K] @ W[N,K]^T ----------
// Block 128x128, k-tile 32, 8 warps (2m x 4n), warp tile 64x32.
// A split into fp16 hi+lo (2 MMA passes), W single fp16.
// 3-stage cp.async pipeline, ONE __syncthreads per k-tile, 2 CTAs/SM.
#define BM 128
#define BN 128
#define BK 32
#define LDS_ROW 40                       // fp16 elems per smem row (32 + 8 pad)
#define TILE_B (128 * LDS_ROW * 2)       // 10240 bytes per 128x32 tile
#define STAGE_B (3 * TILE_B)             // Ah, Al, W
#define STAGES 3
#define SMEM_TOTAL (STAGES * STAGE_B)    // 92160

__device__ __forceinline__ void stage_load(uint32_t sbase,
    const __half* __restrict__ Ah, const __half* __restrict__ Al,
    const __half* __restrict__ W, int k0, int K, int tid)
{
    const __half* srcs[3] = {Ah, Al, W};
    #pragma unroll
    for (int a = 0; a < 3; a++) {
        #pragma unroll
        for (int i = 0; i < 2; i++) {
            int idx = i * 256 + tid;        // 0..511
            int row = idx >> 2;
            int c8  = (idx & 3) * 8;
            const void* g = srcs[a] + (size_t)row * K + k0 + c8;
            uint32_t s = sbase + a * TILE_B + row * (LDS_ROW * 2) + c8 * 2;
            cp16(s, g);
        }
    }
}

__global__ __launch_bounds__(256, 2) void gemm_tc(
    const __half* __restrict__ Ah, const __half* __restrict__ Al,
    const __half* __restrict__ W,
    float* __restrict__ C, int M, int N, int K)
{
    extern __shared__ char smem[];
    uint32_t sb = smem_u32(smem);
    const int tid = threadIdx.x, wid = tid >> 5, lane = tid & 31;
    const int wm = wid >> 2, wn = wid & 3;       // warp 64x32 tile
    const int m0 = blockIdx.y * BM, n0 = blockIdx.x * BN;

    const __half* Ahp = Ah + (size_t)m0 * K;
    const __half* Alp = Al + (size_t)m0 * K;
    const __half* Wp  = W  + (size_t)n0 * K;

    float acc[4][4][4];
    #pragma unroll
    for (int i = 0; i < 4; i++)
        #pragma unroll
        for (int j = 0; j < 4; j++)
            #pragma unroll
            for (int q = 0; q < 4; q++) acc[i][j][q] = 0.f;

    const int T = K / BK;
    stage_load(sb + 0 * STAGE_B, Ahp, Alp, Wp, 0, K, tid);
    cp_commit();
    stage_load(sb + 1 * STAGE_B, Ahp, Alp, Wp, BK, K, tid);
    cp_commit();

    // ldmatrix lane addressing
    const int l15 = lane & 15;
    const int a_khalf = (lane >> 4) & 1;
    const int b_grp = lane >> 3, b_r = lane & 7;
    const int b_row_off = ((b_grp >> 1) << 3) + b_r;
    const int b_kb = (b_grp & 1) * 16;

    for (int t = 0; t < T; t++) {
        cp_wait1();                    // stage t landed
        __syncthreads();
        if (t + 2 < T)
            stage_load(sb + ((t + 2) % STAGES) * STAGE_B, Ahp, Alp, Wp,
                       (t + 2) * BK, K, tid);
        cp_commit();                   // uniform commit keeps group count exact

        uint32_t cur = sb + (t % STAGES) * STAGE_B;
        #pragma unroll
        for (int kk = 0; kk < 2; kk++) {
            uint32_t ah[4][4], al[4][4], wf[2][4];
            #pragma unroll
            for (int mi = 0; mi < 4; mi++) {
                int row = wm * 64 + mi * 16 + l15;
                uint32_t addr = cur + row * (LDS_ROW * 2) + kk * 32 + a_khalf * 16;
                ldm_x4(ah[mi], addr + 0 * TILE_B);
                ldm_x4(al[mi], addr + 1 * TILE_B);
            }
            #pragma unroll
            for (int n2 = 0; n2 < 2; n2++) {
                int row = wn * 32 + n2 * 16 + b_row_off;
                uint32_t addr = cur + row * (LDS_ROW * 2) + kk * 32 + b_kb;
                ldm_x4(wf[n2], addr + 2 * TILE_B);
            }
            #pragma unroll
            for (int mi = 0; mi < 4; mi++)
                #pragma unroll
                for (int ni = 0; ni < 4; ni++) {
                    const uint32_t* bw = &wf[ni >> 1][(ni & 1) * 2];
                    mma_fp16(acc[mi][ni], ah[mi], bw);
                    mma_fp16(acc[mi][ni], al[mi], bw);
                }
        }
    }

    const int g = lane >> 2, tq = lane & 3;
    #pragma unroll
    for (int mi = 0; mi < 4; mi++) {
        #pragma unroll
        for (int ni = 0; ni < 4; ni++) {
            int row = m0 + wm * 64 + mi * 16 + g;
            int col = n0 + wn * 32 + ni * 8 + tq * 2;
            *(float2*)(C + (size_t)row * N + col) =
                make_float2(acc[mi][ni][0], acc[mi][ni][1]);
            *(float2*)(C + (size_t)(row + 8) * N + col) =
                make_float2(acc[mi][ni][2], acc[mi][ni][3]);
        }
    }
}

// ---------------- fp32 -> (hi, lo) fp16 split ----------------
__global__ __launch_bounds__(256) void split_kernel(const float* __restrict__ src,
    __half* __restrict__ hi, __half* __restrict__ lo, int n4)
{
    int i = blockIdx.x * blockDim.x + threadIdx.x;
    if (i >= n4) return;
    float4 v = ((const float4*)src)[i];
    float f[4] = {v.x, v.y, v.z, v.w};
    uint32_t ph[2] = {0, 0}, pl[2] = {0, 0};
    #pragma unroll
    for (int j = 0; j < 4; j++) {
        __half h = __float2half_rn(f[j]);
        __half l = __float2half_rn(f[j] - __half2float(h));
        uint32_t hu = *reinterpret_cast<unsigned short*>(&h);
        uint32_t lu = *reinterpret_cast<unsigned short*>(&l);
        ph[j >> 1] |= hu << ((j & 1) * 16);
        pl[j >> 1] |= lu << ((j & 1) * 16);
    }
    ((uint2*)hi)[i] = make_uint2(ph[0], ph[1]);
    ((uint2*)lo)[i] = make_uint2(pl[0], pl[1]);
}

// ---------------- fp32 -> fp16 convert (weights) ----------------
__global__ __launch_bounds__(256) void cvt_kernel(const float* __restrict__ src,
    __half* __restrict__ dst, int n4)
{
    int i = blockIdx.x * blockDim.x + threadIdx.x;
    if (i >= n4) return;
    float4 v = ((const float4*)src)[i];
    __half2 a = __floats2half2_rn(v.x, v.y);
    __half2 b = __floats2half2_rn(v.z, v.w);
    ((uint2*)dst)[i] = make_uint2(*(uint32_t*)&a, *(uint32_t*)&b);
}

// ---------------- causal depthwise conv (DC=4) + silu ----------------
__global__ __launch_bounds__(256) void conv_silu_kernel(
    const float* __restrict__ cw, const float* __restrict__ cb)
{
    int gid = blockIdx.x * blockDim.x + threadIdx.x;
    if (gid >= M_ * (DI_ / 4)) return;
    int iq = gid & (DI_ / 4 - 1);
    int r  = gid >> 9;
    int i  = iq * 4;
    int b  = r >> 11;
    int l  = r & (L_ - 1);

    float4 bias = *(const float4*)(cb + i);
    float acc[4] = {bias.x, bias.y, bias.z, bias.w};
    float w[4][4];
    #pragma unroll
    for (int j = 0; j < 4; j++) {
        float4 t = *(const float4*)(cw + (i + j) * DC_);
        w[j][0] = t.x; w[j][1] = t.y; w[j][2] = t.z; w[j][3] = t.w;
    }
    #pragma unroll
    for (int k = 0; k < DC_; k++) {
        int ls = l + k - (DC_ - 1);
        if (ls >= 0) {
            float4 xv = *(const float4*)(g_xinner + (size_t)(b * L_ + ls) * N1_ + i);
            acc[0] = fmaf(xv.x, w[0][k], acc[0]);
            acc[1] = fmaf(xv.y, w[1][k], acc[1]);
            acc[2] = fmaf(xv.z, w[2][k], acc[2]);
            acc[3] = fmaf(xv.w, w[3][k], acc[3]);
        }
    }
    float4 o;
    o.x = acc[0] / (1.f + expf(-acc[0]));
    o.y = acc[1] / (1.f + expf(-acc[1]));
    o.z = acc[2] / (1.f + expf(-acc[2]));
    o.w = acc[3] / (1.f + expf(-acc[3]));
    *(float4*)(g_xconv + (size_t)r * DI_ + i) = o;
}

// ---------------- small-N GEMM: dots[8192,48] + row sums ----------------
#define KT2 16
__global__ __launch_bounds__(256) void dbc_kernel(
    const float* __restrict__ dw, const float* __restrict__ bw,
    const float* __restrict__ cw)
{
    __shared__ float As[KT2][128];
    __shared__ float Ws[KT2][48];
    const int tid = threadIdx.x;
    const int m0  = blockIdx.x * 128;
    const int kbase = blockIdx.y * (DI_ / KSPLIT);
    const int r  = tid >> 1;
    const int cg = tid & 1;

    float acc[24];
    #pragma unroll
    for (int j = 0; j < 24; j++) acc[j] = 0.f;
    float rowsum = 0.f;
    const int arow = tid >> 1;
    const int acol = (tid & 1) * 8;

    for (int kt = 0; kt < DI_ / KSPLIT; kt += KT2) {
        int k0 = kbase + kt;
        __syncthreads();
        {
            const float* src = g_xconv + (size_t)(m0 + arow) * DI_ + k0 + acol;
            float4 v0 = *(const float4*)(src);
            float4 v1 = *(const float4*)(src + 4);
            As[acol + 0][arow] = v0.x; As[acol + 1][arow] = v0.y;
            As[acol + 2][arow] = v0.z; As[acol + 3][arow] = v0.w;
            As[acol + 4][arow] = v1.x; As[acol + 5][arow] = v1.y;
            As[acol + 6][arow] = v1.z; As[acol + 7][arow] = v1.w;
            if (tid < 192) {
                int wrow = tid >> 2;
                int wcol = (tid & 3) * 4;
                const float* wp = (wrow < 16) ? dw + wrow * DI_
                               : (wrow < 32) ? bw + (wrow - 16) * DI_
                                             : cw + (wrow - 32) * DI_;
                float4 wv = *(const float4*)(wp + k0 + wcol);
                Ws[wcol + 0][wrow] = wv.x; Ws[wcol + 1][wrow] = wv.y;
                Ws[wcol + 2][wrow] = wv.z; Ws[wcol + 3][wrow] = wv.w;
            }
        }
        __syncthreads();
        #pragma unroll
        for (int k = 0; k < KT2; k++) {
            float a = As[k][r];
            rowsum += a;
            #pragma unroll
            for (int j = 0; j < 24; j++)
                acc[j] = fmaf(a, Ws[k][cg * 24 + j], acc[j]);
        }
    }
    float* pb = g_part + (size_t)blockIdx.y * M_ * 48 + (size_t)(m0 + r) * 48 + cg * 24;
    #pragma unroll
    for (int j = 0; j < 24; j++) pb[j] = acc[j];
    if (cg == 0) g_rspart[blockIdx.y * M_ + m0 + r] = rowsum;
}

// ---------------- reduce partials -> scan coefficients (s-major out) --------
__global__ __launch_bounds__(256) void gu_kernel(
    const float* __restrict__ A_log, const float* __restrict__ delta_b)
{
    int gid = blockIdx.x * blockDim.x + threadIdx.x;
    if (gid >= M_ * DS_) return;
    int s = gid >> 13;              // gid / M_
    int r = gid & (M_ - 1);
    float dd = 0.f, db = 0.f, dc = 0.f, rs = 0.f;
    #pragma unroll
    for (int p = 0; p < KSPLIT; p++) {
        const float* pp = g_part + (size_t)p * M_ * 48 + (size_t)r * 48;
        dd += pp[s];
        db += pp[16 + s];
        dc += pp[32 + s];
        rs += g_rspart[p * M_ + r];
    }
    float z = dd + delta_b[s];
    float delta = (z > 20.f) ? z : log1pf(expf(z));
    float Aval = -expf(A_log[s]);
    size_t o = (size_t)s * M_ + r;
    g_G[o]  = expf(delta * Aval);
    g_U[o]  = delta * db * (rs * (1.f / (float)DI_));
    g_Cs[o] = dc;
}

// ---------------- parallel scan: one block per (b,s), 64 threads ------------
__global__ __launch_bounds__(64) void scan2_kernel()
{
    __shared__ float sG[L_], sU[L_], sC[L_];
    __shared__ float sA[64], sB[64];
    const int b = blockIdx.x >> 4, s = blockIdx.x & 15;
    const int tid = threadIdx.x;
    const size_t base = (size_t)s * M_ + (size_t)b * L_;

    for (int i = tid; i < L_ / 4; i += 64) {
        ((float4*)sG)[i] = *(const float4*)(g_G  + base + i * 4);
        ((float4*)sU)[i] = *(const float4*)(g_U  + base + i * 4);
        ((float4*)sC)[i] = *(const float4*)(g_Cs + base + i * 4);
    }
    __syncthreads();

    const int CH = L_ / 64;   // 32
    const int l0 = tid * CH;
    float A = 1.f, U = 0.f;
    #pragma unroll
    for (int i = 0; i < CH; i++) {
        float gv = sG[l0 + i];
        A *= gv;
        U = fmaf(gv, U, sU[l0 + i]);
    }
    sA[tid] = A; sB[tid] = U;
    __syncthreads();

    #pragma unroll
    for (int d = 1; d < 64; d <<= 1) {
        float a2 = sA[tid], u2 = sB[tid];
        float a1 = 1.f, u1 = 0.f;
        if (tid >= d) { a1 = sA[tid - d]; u1 = sB[tid - d]; }
        __syncthreads();
        sA[tid] = a2 * a1;
        sB[tid] = fmaf(a2, u1, u2);
        __syncthreads();
    }

    float h = (tid == 0) ? 0.f : sB[tid - 1];
    #pragma unroll
    for (int i = 0; i < CH; i++) {
        h = fmaf(sG[l0 + i], h, sU[l0 + i]);
        sU[l0 + i] = h * sC[l0 + i];
    }
    __syncthreads();
    for (int i = tid; i < L_ / 4; i += 64)
        *(float4*)(g_hc + base + i * 4) = ((float4*)sU)[i];
}

// ---------------- y[r] = sum_s hc[s][r] ----------------
__global__ __launch_bounds__(256) void ysum_kernel()
{
    int r = blockIdx.x * blockDim.x + threadIdx.x;
    if (r >= M_) return;
    float acc = 0.f;
    #pragma unroll
    for (int s = 0; s < DS_; s++)
        acc += g_hc[(size_t)s * M_ + r];
    g_y[r] = acc;
}

// ---------------- y_skip = y*silu(gate) + x_conv*D  -> fp16 hi/lo ----------
__global__ __launch_bounds__(256) void yskip_kernel(const float* __restrict__ Dp)
{
    int gid = blockIdx.x * blockDim.x + threadIdx.x;
    if (gid >= M_ * (DI_ / 4)) return;
    int iq = gid & (DI_ / 4 - 1);
    int r  = gid >> 9;
    int i  = iq * 4;
    float4 gt = *(const float4*)(g_xinner + (size_t)r * N1_ + DI_ + i);
    float4 xc = *(const float4*)(g_xconv + (size_t)r * DI_ + i);
    float4 dv = *(const float4*)(Dp + i);
    float yv = g_y[r];
    float f[4];
    f[0] = fmaf(yv, gt.x / (1.f + expf(-gt.x)), xc.x * dv.x);
    f[1] = fmaf(yv, gt.y / (1.f + expf(-gt.y)), xc.y * dv.y);
    f[2] = fmaf(yv, gt.z / (1.f + expf(-gt.z)), xc.z * dv.z);
    f[3] = fmaf(yv, gt.w / (1.f + expf(-gt.w)), xc.w * dv.w);
    uint32_t ph[2] = {0, 0}, pl[2] = {0, 0};
    #pragma unroll
    for (int j = 0; j < 4; j++) {
        __half h = __float2half_rn(f[j]);
        __half l = __float2half_rn(f[j] - __half2float(h));
        uint32_t hu = *reinterpret_cast<unsigned short*>(&h);
        uint32_t lu = *reinterpret_cast<unsigned short*>(&l);
        ph[j >> 1] |= hu << ((j & 1) * 16);
        pl[j >> 1] |= lu << ((j & 1) * 16);
    }
    size_t o = (size_t)r * (DI_ / 4) + iq;
    ((uint2*)g_ysh)[o] = make_uint2(ph[0], ph[1]);
    ((uint2*)g_ysl)[o] = make_uint2(pl[0], pl[1]);
}

// ---------------- launch ----------------
extern "C" void kernel_launch(void* const* d_in, const int* in_sizes, int n_in,
                              void* d_out, int out_size)
{
    const float* x          = (const float*)d_in[0];
    const float* in_proj_w  = (const float*)d_in[1];
    const float* conv_w     = (const float*)d_in[2];
    const float* conv_b     = (const float*)d_in[3];
    const float* A_log      = (const float*)d_in[4];
    const float* Dp         = (const float*)d_in[5];
    const float* delta_w    = (const float*)d_in[6];
    const float* delta_b    = (const float*)d_in[7];
    const float* B_w        = (const float*)d_in[8];
    const float* C_w        = (const float*)d_in[9];
    const float* out_proj_w = (const float*)d_in[10];
    float* out = (float*)d_out;

    float *p_xinner = nullptr;
    __half *p_xh, *p_xl, *p_w1, *p_wo, *p_ysh, *p_ysl;
    cudaGetSymbolAddress((void**)&p_xinner, g_xinner);
    cudaGetSymbolAddress((void**)&p_xh,  g_xh);
    cudaGetSymbolAddress((void**)&p_xl,  g_xl);
    cudaGetSymbolAddress((void**)&p_w1,  g_w1);
    cudaGetSymbolAddress((void**)&p_wo,  g_wo);
    cudaGetSymbolAddress((void**)&p_ysh, g_ysh);
    cudaGetSymbolAddress((void**)&p_ysl, g_ysl);

    cudaFuncSetAttribute(gemm_tc, cudaFuncAttributeMaxDynamicSharedMemorySize, SMEM_TOTAL);

    // 0) split x to hi/lo fp16; convert weights to fp16
    split_kernel<<<(M_ * DM_ / 4 + 255) / 256, 256>>>(x, p_xh, p_xl, M_ * DM_ / 4);
    cvt_kernel<<<(N1_ * DM_ / 4 + 255) / 256, 256>>>(in_proj_w, p_w1, N1_ * DM_ / 4);
    cvt_kernel<<<(DM_ * DI_ / 4 + 255) / 256, 256>>>(out_proj_w, p_wo, DM_ * DI_ / 4);

    // 1) x_inner = x @ in_proj_w^T  [8192,4096]  (HMMA fp16, A split)
    gemm_tc<<<dim3(N1_ / BN, M_ / BM), 256, SMEM_TOTAL>>>(
        p_xh, p_xl, p_w1, p_xinner, M_, N1_, DM_);

    // 2) causal conv + silu
    conv_silu_kernel<<<(M_ * (DI_ / 4) + 255) / 256, 256>>>(conv_w, conv_b);

    // 3) delta/B/C dots + row sums
    dbc_kernel<<<dim3(M_ / 128, KSPLIT), 256>>>(delta_w, B_w, C_w);

    // 4) scan coefficients (s-major)
    gu_kernel<<<(M_ * DS_ + 255) / 256, 256>>>(A_log, delta_b);

    // 5) parallel scan + reduce over states
    scan2_kernel<<<B_ * DS_, 64>>>();
    ysum_kernel<<<(M_ + 255) / 256, 256>>>();

    // 6) gate + skip fuse -> fp16 hi/lo
    yskip_kernel<<<(M_ * (DI_ / 4) + 255) / 256, 256>>>(Dp);

    // 7) out = y_skip @ out_proj_w^T  [8192,1024]  (HMMA fp16, A split)
    gemm_tc<<<dim3(DM_ / BN, M_ / BM), 256, SMEM_TOTAL>>>(
        p_ysh, p_ysl, p_wo, out, M_, DM_, DI_);
}

// round 6
// speedup vs baseline: 5.8155x; 1.4470x over previous
#include <cuda_runtime.h>
#include <cuda_fp16.h>
#include <math.h>
#include <stdint.h>

// ---------------- problem dims ----------------
#define B_   4
#define L_   2048
#define DM_  1024
#define DS_  16
#define DC_  4
#define DI_  2048
#define N1_  4096              // 2*DI
#define M_   (B_ * L_)         // 8192
#define KSPLIT 8

// ---------------- scratch (__device__ globals, no allocation) ----------------
__device__ float g_xinner[(size_t)M_ * N1_];
__device__ float g_xconv [(size_t)M_ * DI_];
__device__ float g_part  [KSPLIT * M_ * 48];
__device__ float g_rspart[KSPLIT * M_];
__device__ float g_G [M_ * DS_];   // s-major: [s][b*L+l]
__device__ float g_U [M_ * DS_];
__device__ float g_Cs[M_ * DS_];
__device__ float g_hc[M_ * DS_];   // h*C, s-major
__device__ float g_y[M_];
__device__ __half g_xf [(size_t)M_  * DM_];
__device__ __half g_w1 [(size_t)N1_ * DM_];
__device__ __half g_wo [(size_t)DM_ * DI_];
__device__ __half g_ys [(size_t)M_  * DI_];

// ---------------- helpers ----------------
__device__ __forceinline__ uint32_t smem_u32(const void* p) {
    uint32_t a;
    asm("{ .reg .u64 t; cvta.to.shared.u64 t, %1; cvt.u32.u64 %0, t; }" : "=r"(a) : "l"(p));
    return a;
}
__device__ __forceinline__ void cp16(uint32_t dst, const void* src) {
    asm volatile("cp.async.cg.shared.global [%0], [%1], 16;" :: "r"(dst), "l"(src));
}
__device__ __forceinline__ void cp_commit() {
    asm volatile("cp.async.commit_group;" ::: "memory");
}
__device__ __forceinline__ void cp_wait2() {
    asm volatile("cp.async.wait_group 2;" ::: "memory");
}
__device__ __forceinline__ void ldm_x4(uint32_t* r, uint32_t addr) {
    asm volatile("ldmatrix.sync.aligned.m8n8.x4.shared.b16 {%0,%1,%2,%3}, [%4];"
        : "=r"(r[0]), "=r"(r[1]), "=r"(r[2]), "=r"(r[3]) : "r"(addr));
}
__device__ __forceinline__ void mma_fp16(float* c, const uint32_t* a, const uint32_t* b) {
    asm volatile(
        "mma.sync.aligned.m16n8k16.row.col.f32.f16.f16.f32 "
        "{%0,%1,%2,%3}, {%4,%5,%6,%7}, {%8,%9}, {%0,%1,%2,%3};"
        : "+f"(c[0]), "+f"(c[1]), "+f"(c[2]), "+f"(c[3])
        : "r"(a[0]), "r"(a[1]), "r"(a[2]), "r"(a[3]), "r"(b[0]), "r"(b[1]));
}

// ---------------- HMMA fp16 GEMM: C[M,N] = A[M,K] @ W[N,K]^T ----------------
// Block 128x128, k-tile 32, 8 warps (2m x 4n), warp tile 64x32.
// 4-stage cp.async pipeline, ONE __syncthreads per k-tile, 2 CTAs/SM.
#define BM 128
#define BN 128
#define BK 32
#define LDS_ROW 40                       // fp16 elems per smem row (32 + 8 pad)
#define TILE_B (128 * LDS_ROW * 2)       // 10240 bytes per 128x32 tile
#define STAGE_B (2 * TILE_B)             // A, W
#define STAGES 4
#define SMEM_TOTAL (STAGES * STAGE_B)    // 81920

__device__ __forceinline__ void stage_load(uint32_t sbase,
    const __half* __restrict__ A, const __half* __restrict__ W,
    int k0, int K, int tid)
{
    const __half* srcs[2] = {A, W};
    #pragma unroll
    for (int a = 0; a < 2; a++) {
        #pragma unroll
        for (int i = 0; i < 2; i++) {
            int idx = i * 256 + tid;        // 0..511
            int row = idx >> 2;
            int c8  = (idx & 3) * 8;
            const void* g = srcs[a] + (size_t)row * K + k0 + c8;
            uint32_t s = sbase + a * TILE_B + row * (LDS_ROW * 2) + c8 * 2;
            cp16(s, g);
        }
    }
}

__global__ __launch_bounds__(256, 2) void gemm_tc(
    const __half* __restrict__ A, const __half* __restrict__ W,
    float* __restrict__ C, int M, int N, int K)
{
    extern __shared__ char smem[];
    uint32_t sb = smem_u32(smem);
    const int tid = threadIdx.x, wid = tid >> 5, lane = tid & 31;
    const int wm = wid >> 2, wn = wid & 3;       // warp 64x32 tile
    const int m0 = blockIdx.y * BM, n0 = blockIdx.x * BN;

    const __half* Ap = A + (size_t)m0 * K;
    const __half* Wp = W + (size_t)n0 * K;

    float acc[4][4][4];
    #pragma unroll
    for (int i = 0; i < 4; i++)
        #pragma unroll
        for (int j = 0; j < 4; j++)
            #pragma unroll
            for (int q = 0; q < 4; q++) acc[i][j][q] = 0.f;

    const int T = K / BK;
    #pragma unroll
    for (int p = 0; p < 3; p++) {
        stage_load(sb + p * STAGE_B, Ap, Wp, p * BK, K, tid);
        cp_commit();
    }

    // ldmatrix lane addressing
    const int l15 = lane & 15;
    const int a_khalf = (lane >> 4) & 1;
    const int b_grp = lane >> 3, b_r = lane & 7;
    const int b_row_off = ((b_grp >> 1) << 3) + b_r;
    const int b_kb = (b_grp & 1) * 16;

    for (int t = 0; t < T; t++) {
        cp_wait2();                    // stage t landed (<=2 newer in flight)
        __syncthreads();
        if (t + 3 < T)
            stage_load(sb + ((t + 3) % STAGES) * STAGE_B, Ap, Wp,
                       (t + 3) * BK, K, tid);
        cp_commit();                   // uniform commit keeps group count exact

        uint32_t cur = sb + (t % STAGES) * STAGE_B;
        #pragma unroll
        for (int kk = 0; kk < 2; kk++) {
            uint32_t af[4][4], wf[2][4];
            #pragma unroll
            for (int mi = 0; mi < 4; mi++) {
                int row = wm * 64 + mi * 16 + l15;
                uint32_t addr = cur + row * (LDS_ROW * 2) + kk * 32 + a_khalf * 16;
                ldm_x4(af[mi], addr);
            }
            #pragma unroll
            for (int n2 = 0; n2 < 2; n2++) {
                int row = wn * 32 + n2 * 16 + b_row_off;
                uint32_t addr = cur + row * (LDS_ROW * 2) + kk * 32 + b_kb;
                ldm_x4(wf[n2], addr + TILE_B);
            }
            #pragma unroll
            for (int mi = 0; mi < 4; mi++)
                #pragma unroll
                for (int ni = 0; ni < 4; ni++)
                    mma_fp16(acc[mi][ni], af[mi], &wf[ni >> 1][(ni & 1) * 2]);
        }
    }

    const int g = lane >> 2, tq = lane & 3;
    #pragma unroll
    for (int mi = 0; mi < 4; mi++) {
        #pragma unroll
        for (int ni = 0; ni < 4; ni++) {
            int row = m0 + wm * 64 + mi * 16 + g;
            int col = n0 + wn * 32 + ni * 8 + tq * 2;
            *(float2*)(C + (size_t)row * N + col) =
                make_float2(acc[mi][ni][0], acc[mi][ni][1]);
            *(float2*)(C + (size_t)(row + 8) * N + col) =
                make_float2(acc[mi][ni][2], acc[mi][ni][3]);
        }
    }
}

// ---------------- fp32 -> fp16 convert ----------------
__global__ __launch_bounds__(256) void cvt_kernel(const float* __restrict__ src,
    __half* __restrict__ dst, int n4)
{
    int i = blockIdx.x * blockDim.x + threadIdx.x;
    if (i >= n4) return;
    float4 v = ((const float4*)src)[i];
    __half2 a = __floats2half2_rn(v.x, v.y);
    __half2 b = __floats2half2_rn(v.z, v.w);
    ((uint2*)dst)[i] = make_uint2(*(uint32_t*)&a, *(uint32_t*)&b);
}

// ---------------- causal depthwise conv (DC=4) + silu ----------------
__global__ __launch_bounds__(256) void conv_silu_kernel(
    const float* __restrict__ cw, const float* __restrict__ cb)
{
    int gid = blockIdx.x * blockDim.x + threadIdx.x;
    if (gid >= M_ * (DI_ / 4)) return;
    int iq = gid & (DI_ / 4 - 1);
    int r  = gid >> 9;
    int i  = iq * 4;
    int b  = r >> 11;
    int l  = r & (L_ - 1);

    float4 bias = *(const float4*)(cb + i);
    float acc[4] = {bias.x, bias.y, bias.z, bias.w};
    float w[4][4];
    #pragma unroll
    for (int j = 0; j < 4; j++) {
        float4 t = *(const float4*)(cw + (i + j) * DC_);
        w[j][0] = t.x; w[j][1] = t.y; w[j][2] = t.z; w[j][3] = t.w;
    }
    #pragma unroll
    for (int k = 0; k < DC_; k++) {
        int ls = l + k - (DC_ - 1);
        if (ls >= 0) {
            float4 xv = *(const float4*)(g_xinner + (size_t)(b * L_ + ls) * N1_ + i);
            acc[0] = fmaf(xv.x, w[0][k], acc[0]);
            acc[1] = fmaf(xv.y, w[1][k], acc[1]);
            acc[2] = fmaf(xv.z, w[2][k], acc[2]);
            acc[3] = fmaf(xv.w, w[3][k], acc[3]);
        }
    }
    float4 o;
    o.x = acc[0] / (1.f + expf(-acc[0]));
    o.y = acc[1] / (1.f + expf(-acc[1]));
    o.z = acc[2] / (1.f + expf(-acc[2]));
    o.w = acc[3] / (1.f + expf(-acc[3]));
    *(float4*)(g_xconv + (size_t)r * DI_ + i) = o;
}

// ---------------- small-N GEMM: dots[8192,48] + row sums ----------------
#define KT2 16
__global__ __launch_bounds__(256) void dbc_kernel(
    const float* __restrict__ dw, const float* __restrict__ bw,
    const float* __restrict__ cw)
{
    __shared__ float As[KT2][128];
    __shared__ float Ws[KT2][48];
    const int tid = threadIdx.x;
    const int m0  = blockIdx.x * 128;
    const int kbase = blockIdx.y * (DI_ / KSPLIT);
    const int r  = tid >> 1;
    const int cg = tid & 1;

    float acc[24];
    #pragma unroll
    for (int j = 0; j < 24; j++) acc[j] = 0.f;
    float rowsum = 0.f;
    const int arow = tid >> 1;
    const int acol = (tid & 1) * 8;

    for (int kt = 0; kt < DI_ / KSPLIT; kt += KT2) {
        int k0 = kbase + kt;
        __syncthreads();
        {
            const float* src = g_xconv + (size_t)(m0 + arow) * DI_ + k0 + acol;
            float4 v0 = *(const float4*)(src);
            float4 v1 = *(const float4*)(src + 4);
            As[acol + 0][arow] = v0.x; As[acol + 1][arow] = v0.y;
            As[acol + 2][arow] = v0.z; As[acol + 3][arow] = v0.w;
            As[acol + 4][arow] = v1.x; As[acol + 5][arow] = v1.y;
            As[acol + 6][arow] = v1.z; As[acol + 7][arow] = v1.w;
            if (tid < 192) {
                int wrow = tid >> 2;
                int wcol = (tid & 3) * 4;
                const float* wp = (wrow < 16) ? dw + wrow * DI_
                               : (wrow < 32) ? bw + (wrow - 16) * DI_
                                             : cw + (wrow - 32) * DI_;
                float4 wv = *(const float4*)(wp + k0 + wcol);
                Ws[wcol + 0][wrow] = wv.x; Ws[wcol + 1][wrow] = wv.y;
                Ws[wcol + 2][wrow] = wv.z; Ws[wcol + 3][wrow] = wv.w;
            }
        }
        __syncthreads();
        #pragma unroll
        for (int k = 0; k < KT2; k++) {
            float a = As[k][r];
            rowsum += a;
            #pragma unroll
            for (int j = 0; j < 24; j++)
                acc[j] = fmaf(a, Ws[k][cg * 24 + j], acc[j]);
        }
    }
    float* pb = g_part + (size_t)blockIdx.y * M_ * 48 + (size_t)(m0 + r) * 48 + cg * 24;
    #pragma unroll
    for (int j = 0; j < 24; j++) pb[j] = acc[j];
    if (cg == 0) g_rspart[blockIdx.y * M_ + m0 + r] = rowsum;
}

// ---------------- reduce partials -> scan coefficients (s-major out) --------
__global__ __launch_bounds__(256) void gu_kernel(
    const float* __restrict__ A_log, const float* __restrict__ delta_b)
{
    int gid = blockIdx.x * blockDim.x + threadIdx.x;
    if (gid >= M_ * DS_) return;
    int s = gid >> 13;              // gid / M_
    int r = gid & (M_ - 1);
    float dd = 0.f, db = 0.f, dc = 0.f, rs = 0.f;
    #pragma unroll
    for (int p = 0; p < KSPLIT; p++) {
        const float* pp = g_part + (size_t)p * M_ * 48 + (size_t)r * 48;
        dd += pp[s];
        db += pp[16 + s];
        dc += pp[32 + s];
        rs += g_rspart[p * M_ + r];
    }
    float z = dd + delta_b[s];
    float delta = (z > 20.f) ? z : log1pf(expf(z));
    float Aval = -expf(A_log[s]);
    size_t o = (size_t)s * M_ + r;
    g_G[o]  = expf(delta * Aval);
    g_U[o]  = delta * db * (rs * (1.f / (float)DI_));
    g_Cs[o] = dc;
}

// ---------------- parallel scan: one block per (b,s), 64 threads ------------
__global__ __launch_bounds__(64) void scan2_kernel()
{
    __shared__ float sG[L_], sU[L_], sC[L_];
    __shared__ float sA[64], sB[64];
    const int b = blockIdx.x >> 4, s = blockIdx.x & 15;
    const int tid = threadIdx.x;
    const size_t base = (size_t)s * M_ + (size_t)b * L_;

    for (int i = tid; i < L_ / 4; i += 64) {
        ((float4*)sG)[i] = *(const float4*)(g_G  + base + i * 4);
        ((float4*)sU)[i] = *(const float4*)(g_U  + base + i * 4);
        ((float4*)sC)[i] = *(const float4*)(g_Cs + base + i * 4);
    }
    __syncthreads();

    const int CH = L_ / 64;   // 32
    const int l0 = tid * CH;
    float A = 1.f, U = 0.f;
    #pragma unroll
    for (int i = 0; i < CH; i++) {
        float gv = sG[l0 + i];
        A *= gv;
        U = fmaf(gv, U, sU[l0 + i]);
    }
    sA[tid] = A; sB[tid] = U;
    __syncthreads();

    #pragma unroll
    for (int d = 1; d < 64; d <<= 1) {
        float a2 = sA[tid], u2 = sB[tid];
        float a1 = 1.f, u1 = 0.f;
        if (tid >= d) { a1 = sA[tid - d]; u1 = sB[tid - d]; }
        __syncthreads();
        sA[tid] = a2 * a1;
        sB[tid] = fmaf(a2, u1, u2);
        __syncthreads();
    }

    float h = (tid == 0) ? 0.f : sB[tid - 1];
    #pragma unroll
    for (int i = 0; i < CH; i++) {
        h = fmaf(sG[l0 + i], h, sU[l0 + i]);
        sU[l0 + i] = h * sC[l0 + i];
    }
    __syncthreads();
    for (int i = tid; i < L_ / 4; i += 64)
        *(float4*)(g_hc + base + i * 4) = ((float4*)sU)[i];
}

// ---------------- y[r] = sum_s hc[s][r] ----------------
__global__ __launch_bounds__(256) void ysum_kernel()
{
    int r = blockIdx.x * blockDim.x + threadIdx.x;
    if (r >= M_) return;
    float acc = 0.f;
    #pragma unroll
    for (int s = 0; s < DS_; s++)
        acc += g_hc[(size_t)s * M_ + r];
    g_y[r] = acc;
}

// ---------------- y_skip = y*silu(gate) + x_conv*D  -> fp16 ----------------
__global__ __launch_bounds__(256) void yskip_kernel(const float* __restrict__ Dp)
{
    int gid = blockIdx.x * blockDim.x + threadIdx.x;
    if (gid >= M_ * (DI_ / 4)) return;
    int iq = gid & (DI_ / 4 - 1);
    int r  = gid >> 9;
    int i  = iq * 4;
    float4 gt = *(const float4*)(g_xinner + (size_t)r * N1_ + DI_ + i);
    float4 xc = *(const float4*)(g_xconv + (size_t)r * DI_ + i);
    float4 dv = *(const float4*)(Dp + i);
    float yv = g_y[r];
    float f0 = fmaf(yv, gt.x / (1.f + expf(-gt.x)), xc.x * dv.x);
    float f1 = fmaf(yv, gt.y / (1.f + expf(-gt.y)), xc.y * dv.y);
    float f2 = fmaf(yv, gt.z / (1.f + expf(-gt.z)), xc.z * dv.z);
    float f3 = fmaf(yv, gt.w / (1.f + expf(-gt.w)), xc.w * dv.w);
    __half2 a = __floats2half2_rn(f0, f1);
    __half2 b = __floats2half2_rn(f2, f3);
    size_t o = (size_t)r * (DI_ / 4) + iq;
    ((uint2*)g_ys)[o] = make_uint2(*(uint32_t*)&a, *(uint32_t*)&b);
}

// ---------------- launch ----------------
extern "C" void kernel_launch(void* const* d_in, const int* in_sizes, int n_in,
                              void* d_out, int out_size)
{
    const float* x          = (const float*)d_in[0];
    const float* in_proj_w  = (const float*)d_in[1];
    const float* conv_w     = (const float*)d_in[2];
    const float* conv_b     = (const float*)d_in[3];
    const float* A_log      = (const float*)d_in[4];
    const float* Dp         = (const float*)d_in[5];
    const float* delta_w    = (const float*)d_in[6];
    const float* delta_b    = (const float*)d_in[7];
    const float* B_w        = (const float*)d_in[8];
    const float* C_w        = (const float*)d_in[9];
    const float* out_proj_w = (const float*)d_in[10];
    float* out = (float*)d_out;

    float *p_xinner = nullptr;
    __half *p_xf, *p_w1, *p_wo, *p_ys;
    cudaGetSymbolAddress((void**)&p_xinner, g_xinner);
    cudaGetSymbolAddress((void**)&p_xf, g_xf);
    cudaGetSymbolAddress((void**)&p_w1, g_w1);
    cudaGetSymbolAddress((void**)&p_wo, g_wo);
    cudaGetSymbolAddress((void**)&p_ys, g_ys);

    cudaFuncSetAttribute(gemm_tc, cudaFuncAttributeMaxDynamicSharedMemorySize, SMEM_TOTAL);

    // 0) convert x and weights to fp16
    cvt_kernel<<<(M_ * DM_ / 4 + 255) / 256, 256>>>(x, p_xf, M_ * DM_ / 4);
    cvt_kernel<<<(N1_ * DM_ / 4 + 255) / 256, 256>>>(in_proj_w, p_w1, N1_ * DM_ / 4);
    cvt_kernel<<<(DM_ * DI_ / 4 + 255) / 256, 256>>>(out_proj_w, p_wo, DM_ * DI_ / 4);

    // 1) x_inner = x @ in_proj_w^T  [8192,4096]  (HMMA fp16)
    gemm_tc<<<dim3(N1_ / BN, M_ / BM), 256, SMEM_TOTAL>>>(
        p_xf, p_w1, p_xinner, M_, N1_, DM_);

    // 2) causal conv + silu
    conv_silu_kernel<<<(M_ * (DI_ / 4) + 255) / 256, 256>>>(conv_w, conv_b);

    // 3) delta/B/C dots + row sums
    dbc_kernel<<<dim3(M_ / 128, KSPLIT), 256>>>(delta_w, B_w, C_w);

    // 4) scan coefficients (s-major)
    gu_kernel<<<(M_ * DS_ + 255) / 256, 256>>>(A_log, delta_b);

    // 5) parallel scan + reduce over states
    scan2_kernel<<<B_ * DS_, 64>>>();
    ysum_kernel<<<(M_ + 255) / 256, 256>>>();

    // 6) gate + skip fuse -> fp16
    yskip_kernel<<<(M_ * (DI_ / 4) + 255) / 256, 256>>>(Dp);

    // 7) out = y_skip @ out_proj_w^T  [8192,1024]  (HMMA fp16)
    gemm_tc<<<dim3(DM_ / BN, M_ / BM), 256, SMEM_TOTAL>>>(
        p_ys, p_wo, out, M_, DM_, DI_);
}

// round 7
// speedup vs baseline: 6.3726x; 1.0958x over previous
#include <cuda_runtime.h>
#include <cuda_fp16.h>
#include <math.h>
#include <stdint.h>

// ---------------- problem dims ----------------
#define B_   4
#define L_   2048
#define DM_  1024
#define DS_  16
#define DC_  4
#define DI_  2048
#define N1_  4096              // 2*DI
#define M_   (B_ * L_)         // 8192
#define KSPLIT 8

// ---------------- scratch (__device__ globals, no allocation) ----------------
__device__ __half g_xinner[(size_t)M_ * N1_];    // fp16 now
__device__ float g_xconv [(size_t)M_ * DI_];
__device__ float g_part  [KSPLIT * M_ * 48];
__device__ float g_rspart[KSPLIT * M_];
__device__ float g_G [M_ * DS_];   // s-major: [s][b*L+l]
__device__ float g_U [M_ * DS_];
__device__ float g_Cs[M_ * DS_];
__device__ float g_hc[M_ * DS_];   // h*C, s-major
__device__ float g_y[M_];
__device__ __half g_xf [(size_t)M_  * DM_];
__device__ __half g_w1 [(size_t)N1_ * DM_];
__device__ __half g_wo [(size_t)DM_ * DI_];
__device__ __half g_ys [(size_t)M_  * DI_];

// ---------------- helpers ----------------
__device__ __forceinline__ uint32_t smem_u32(const void* p) {
    uint32_t a;
    asm("{ .reg .u64 t; cvta.to.shared.u64 t, %1; cvt.u32.u64 %0, t; }" : "=r"(a) : "l"(p));
    return a;
}
__device__ __forceinline__ void cp16(uint32_t dst, const void* src) {
    asm volatile("cp.async.cg.shared.global [%0], [%1], 16;" :: "r"(dst), "l"(src));
}
__device__ __forceinline__ void cp_commit() {
    asm volatile("cp.async.commit_group;" ::: "memory");
}
__device__ __forceinline__ void cp_wait1() {
    asm volatile("cp.async.wait_group 1;" ::: "memory");
}
__device__ __forceinline__ void ldm_x4(uint32_t* r, uint32_t addr) {
    asm volatile("ldmatrix.sync.aligned.m8n8.x4.shared.b16 {%0,%1,%2,%3}, [%4];"
        : "=r"(r[0]), "=r"(r[1]), "=r"(r[2]), "=r"(r[3]) : "r"(addr));
}
__device__ __forceinline__ void mma_fp16(float* c, const uint32_t* a, const uint32_t* b) {
    asm volatile(
        "mma.sync.aligned.m16n8k16.row.col.f32.f16.f16.f32 "
        "{%0,%1,%2,%3}, {%4,%5,%6,%7}, {%8,%9}, {%0,%1,%2,%3};"
        : "+f"(c[0]), "+f"(c[1]), "+f"(c[2]), "+f"(c[3])
        : "r"(a[0]), "r"(a[1]), "r"(a[2]), "r"(a[3]), "r"(b[0]), "r"(b[1]));
}

// ---------------- HMMA fp16 GEMM: C[M,N] = A[M,K] @ W[N,K]^T ----------------
// Block 128x128, k-tile 64, 8 warps (2m x 4n), warp tile 64x32.
// 3-stage cp.async pipeline, ONE __syncthreads per k-tile, 2 CTAs/SM.
#define BM 128
#define BN 128
#define BK 64
#define LDS_ROW 72                       // fp16 elems per smem row (64 + 8 pad)
#define TILE_B (128 * LDS_ROW * 2)       // 18432 bytes per 128x64 tile
#define STAGE_B (2 * TILE_B)             // A, W
#define STAGES 3
#define SMEM_TOTAL (STAGES * STAGE_B)    // 110592

__device__ __forceinline__ void stage_load(uint32_t sbase,
    const __half* __restrict__ A, const __half* __restrict__ W,
    int k0, int K, int tid)
{
    const __half* srcs[2] = {A, W};
    #pragma unroll
    for (int a = 0; a < 2; a++) {
        #pragma unroll
        for (int i = 0; i < 4; i++) {
            int idx = i * 256 + tid;        // 0..1023
            int row = idx >> 3;             // 0..127
            int c8  = (idx & 7) * 8;        // 0..56
            const void* g = srcs[a] + (size_t)row * K + k0 + c8;
            uint32_t s = sbase + a * TILE_B + row * (LDS_ROW * 2) + c8 * 2;
            cp16(s, g);
        }
    }
}

template <typename TOut>
__global__ __launch_bounds__(256, 2) void gemm_tc(
    const __half* __restrict__ A, const __half* __restrict__ W,
    TOut* __restrict__ C, int M, int N, int K)
{
    extern __shared__ char smem[];
    uint32_t sb = smem_u32(smem);
    const int tid = threadIdx.x, wid = tid >> 5, lane = tid & 31;
    const int wm = wid >> 2, wn = wid & 3;       // warp 64x32 tile
    const int m0 = blockIdx.y * BM, n0 = blockIdx.x * BN;

    const __half* Ap = A + (size_t)m0 * K;
    const __half* Wp = W + (size_t)n0 * K;

    float acc[4][4][4];
    #pragma unroll
    for (int i = 0; i < 4; i++)
        #pragma unroll
        for (int j = 0; j < 4; j++)
            #pragma unroll
            for (int q = 0; q < 4; q++) acc[i][j][q] = 0.f;

    const int T = K / BK;
    stage_load(sb + 0 * STAGE_B, Ap, Wp, 0, K, tid);
    cp_commit();
    stage_load(sb + 1 * STAGE_B, Ap, Wp, BK, K, tid);
    cp_commit();

    // ldmatrix lane addressing
    const int l15 = lane & 15;
    const int a_khalf = (lane >> 4) & 1;
    const int b_grp = lane >> 3, b_r = lane & 7;
    const int b_row_off = ((b_grp >> 1) << 3) + b_r;
    const int b_kb = (b_grp & 1) * 16;

    for (int t = 0; t < T; t++) {
        cp_wait1();                    // stage t landed (<=1 newer in flight)
        __syncthreads();               // all warps done with slot being reloaded
        if (t + 2 < T)
            stage_load(sb + ((t + 2) % STAGES) * STAGE_B, Ap, Wp,
                       (t + 2) * BK, K, tid);
        cp_commit();                   // uniform commit keeps group count exact

        uint32_t cur = sb + (t % STAGES) * STAGE_B;
        #pragma unroll
        for (int kk = 0; kk < 4; kk++) {
            uint32_t af[4][4], wf[2][4];
            #pragma unroll
            for (int mi = 0; mi < 4; mi++) {
                int row = wm * 64 + mi * 16 + l15;
                uint32_t addr = cur + row * (LDS_ROW * 2) + kk * 32 + a_khalf * 16;
                ldm_x4(af[mi], addr);
            }
            #pragma unroll
            for (int n2 = 0; n2 < 2; n2++) {
                int row = wn * 32 + n2 * 16 + b_row_off;
                uint32_t addr = cur + row * (LDS_ROW * 2) + kk * 32 + b_kb;
                ldm_x4(wf[n2], addr + TILE_B);
            }
            #pragma unroll
            for (int mi = 0; mi < 4; mi++)
                #pragma unroll
                for (int ni = 0; ni < 4; ni++)
                    mma_fp16(acc[mi][ni], af[mi], &wf[ni >> 1][(ni & 1) * 2]);
        }
    }

    const int g = lane >> 2, tq = lane & 3;
    #pragma unroll
    for (int mi = 0; mi < 4; mi++) {
        #pragma unroll
        for (int ni = 0; ni < 4; ni++) {
            int row = m0 + wm * 64 + mi * 16 + g;
            int col = n0 + wn * 32 + ni * 8 + tq * 2;
            if (sizeof(TOut) == 4) {
                float* cp0 = (float*)C + (size_t)row * N + col;
                *(float2*)cp0 = make_float2(acc[mi][ni][0], acc[mi][ni][1]);
                *(float2*)((float*)C + (size_t)(row + 8) * N + col) =
                    make_float2(acc[mi][ni][2], acc[mi][ni][3]);
            } else {
                __half2 h0 = __floats2half2_rn(acc[mi][ni][0], acc[mi][ni][1]);
                __half2 h1 = __floats2half2_rn(acc[mi][ni][2], acc[mi][ni][3]);
                *(uint32_t*)((__half*)C + (size_t)row * N + col) = *(uint32_t*)&h0;
                *(uint32_t*)((__half*)C + (size_t)(row + 8) * N + col) = *(uint32_t*)&h1;
            }
        }
    }
}

// ---------------- fp32 -> fp16 convert ----------------
__global__ __launch_bounds__(256) void cvt_kernel(const float* __restrict__ src,
    __half* __restrict__ dst, int n4)
{
    int i = blockIdx.x * blockDim.x + threadIdx.x;
    if (i >= n4) return;
    float4 v = ((const float4*)src)[i];
    __half2 a = __floats2half2_rn(v.x, v.y);
    __half2 b = __floats2half2_rn(v.z, v.w);
    ((uint2*)dst)[i] = make_uint2(*(uint32_t*)&a, *(uint32_t*)&b);
}

// ---------------- causal depthwise conv (DC=4) + silu (fp16 in, fp32 out) ---
__global__ __launch_bounds__(256) void conv_silu_kernel(
    const float* __restrict__ cw, const float* __restrict__ cb)
{
    int gid = blockIdx.x * blockDim.x + threadIdx.x;
    if (gid >= M_ * (DI_ / 4)) return;
    int iq = gid & (DI_ / 4 - 1);
    int r  = gid >> 9;
    int i  = iq * 4;
    int b  = r >> 11;
    int l  = r & (L_ - 1);

    float4 bias = *(const float4*)(cb + i);
    float acc[4] = {bias.x, bias.y, bias.z, bias.w};
    float w[4][4];
    #pragma unroll
    for (int j = 0; j < 4; j++) {
        float4 t = *(const float4*)(cw + (i + j) * DC_);
        w[j][0] = t.x; w[j][1] = t.y; w[j][2] = t.z; w[j][3] = t.w;
    }
    #pragma unroll
    for (int k = 0; k < DC_; k++) {
        int ls = l + k - (DC_ - 1);
        if (ls >= 0) {
            uint2 raw = *(const uint2*)(g_xinner + (size_t)(b * L_ + ls) * N1_ + i);
            __half2 h0 = *(__half2*)&raw.x;
            __half2 h1 = *(__half2*)&raw.y;
            float2 v0 = __half22float2(h0);
            float2 v1 = __half22float2(h1);
            acc[0] = fmaf(v0.x, w[0][k], acc[0]);
            acc[1] = fmaf(v0.y, w[1][k], acc[1]);
            acc[2] = fmaf(v1.x, w[2][k], acc[2]);
            acc[3] = fmaf(v1.y, w[3][k], acc[3]);
        }
    }
    float4 o;
    o.x = acc[0] / (1.f + expf(-acc[0]));
    o.y = acc[1] / (1.f + expf(-acc[1]));
    o.z = acc[2] / (1.f + expf(-acc[2]));
    o.w = acc[3] / (1.f + expf(-acc[3]));
    *(float4*)(g_xconv + (size_t)r * DI_ + i) = o;
}

// ---------------- small-N GEMM: dots[8192,48] + row sums ----------------
#define KT2 16
__global__ __launch_bounds__(256) void dbc_kernel(
    const float* __restrict__ dw, const float* __restrict__ bw,
    const float* __restrict__ cw)
{
    __shared__ float As[KT2][128];
    __shared__ float Ws[KT2][48];
    const int tid = threadIdx.x;
    const int m0  = blockIdx.x * 128;
    const int kbase = blockIdx.y * (DI_ / KSPLIT);
    const int r  = tid >> 1;
    const int cg = tid & 1;

    float acc[24];
    #pragma unroll
    for (int j = 0; j < 24; j++) acc[j] = 0.f;
    float rowsum = 0.f;
    const int arow = tid >> 1;
    const int acol = (tid & 1) * 8;

    for (int kt = 0; kt < DI_ / KSPLIT; kt += KT2) {
        int k0 = kbase + kt;
        __syncthreads();
        {
            const float* src = g_xconv + (size_t)(m0 + arow) * DI_ + k0 + acol;
            float4 v0 = *(const float4*)(src);
            float4 v1 = *(const float4*)(src + 4);
            As[acol + 0][arow] = v0.x; As[acol + 1][arow] = v0.y;
            As[acol + 2][arow] = v0.z; As[acol + 3][arow] = v0.w;
            As[acol + 4][arow] = v1.x; As[acol + 5][arow] = v1.y;
            As[acol + 6][arow] = v1.z; As[acol + 7][arow] = v1.w;
            if (tid < 192) {
                int wrow = tid >> 2;
                int wcol = (tid & 3) * 4;
                const float* wp = (wrow < 16) ? dw + wrow * DI_
                               : (wrow < 32) ? bw + (wrow - 16) * DI_
                                             : cw + (wrow - 32) * DI_;
                float4 wv = *(const float4*)(wp + k0 + wcol);
                Ws[wcol + 0][wrow] = wv.x; Ws[wcol + 1][wrow] = wv.y;
                Ws[wcol + 2][wrow] = wv.z; Ws[wcol + 3][wrow] = wv.w;
            }
        }
        __syncthreads();
        #pragma unroll
        for (int k = 0; k < KT2; k++) {
            float a = As[k][r];
            rowsum += a;
            #pragma unroll
            for (int j = 0; j < 24; j++)
                acc[j] = fmaf(a, Ws[k][cg * 24 + j], acc[j]);
        }
    }
    float* pb = g_part + (size_t)blockIdx.y * M_ * 48 + (size_t)(m0 + r) * 48 + cg * 24;
    #pragma unroll
    for (int j = 0; j < 24; j++) pb[j] = acc[j];
    if (cg == 0) g_rspart[blockIdx.y * M_ + m0 + r] = rowsum;
}

// ---------------- reduce partials -> scan coefficients (s-major out) --------
__global__ __launch_bounds__(256) void gu_kernel(
    const float* __restrict__ A_log, const float* __restrict__ delta_b)
{
    int gid = blockIdx.x * blockDim.x + threadIdx.x;
    if (gid >= M_ * DS_) return;
    int s = gid >> 13;              // gid / M_
    int r = gid & (M_ - 1);
    float dd = 0.f, db = 0.f, dc = 0.f, rs = 0.f;
    #pragma unroll
    for (int p = 0; p < KSPLIT; p++) {
        const float* pp = g_part + (size_t)p * M_ * 48 + (size_t)r * 48;
        dd += pp[s];
        db += pp[16 + s];
        dc += pp[32 + s];
        rs += g_rspart[p * M_ + r];
    }
    float z = dd + delta_b[s];
    float delta = (z > 20.f) ? z : log1pf(expf(z));
    float Aval = -expf(A_log[s]);
    size_t o = (size_t)s * M_ + r;
    g_G[o]  = expf(delta * Aval);
    g_U[o]  = delta * db * (rs * (1.f / (float)DI_));
    g_Cs[o] = dc;
}

// ---------------- parallel scan: one block per (b,s), 64 threads ------------
__global__ __launch_bounds__(64) void scan2_kernel()
{
    __shared__ float sG[L_], sU[L_], sC[L_];
    __shared__ float sA[64], sB[64];
    const int b = blockIdx.x >> 4, s = blockIdx.x & 15;
    const int tid = threadIdx.x;
    const size_t base = (size_t)s * M_ + (size_t)b * L_;

    for (int i = tid; i < L_ / 4; i += 64) {
        ((float4*)sG)[i] = *(const float4*)(g_G  + base + i * 4);
        ((float4*)sU)[i] = *(const float4*)(g_U  + base + i * 4);
        ((float4*)sC)[i] = *(const float4*)(g_Cs + base + i * 4);
    }
    __syncthreads();

    const int CH = L_ / 64;   // 32
    const int l0 = tid * CH;
    float A = 1.f, U = 0.f;
    #pragma unroll
    for (int i = 0; i < CH; i++) {
        float gv = sG[l0 + i];
        A *= gv;
        U = fmaf(gv, U, sU[l0 + i]);
    }
    sA[tid] = A; sB[tid] = U;
    __syncthreads();

    #pragma unroll
    for (int d = 1; d < 64; d <<= 1) {
        float a2 = sA[tid], u2 = sB[tid];
        float a1 = 1.f, u1 = 0.f;
        if (tid >= d) { a1 = sA[tid - d]; u1 = sB[tid - d]; }
        __syncthreads();
        sA[tid] = a2 * a1;
        sB[tid] = fmaf(a2, u1, u2);
        __syncthreads();
    }

    float h = (tid == 0) ? 0.f : sB[tid - 1];
    #pragma unroll
    for (int i = 0; i < CH; i++) {
        h = fmaf(sG[l0 + i], h, sU[l0 + i]);
        sU[l0 + i] = h * sC[l0 + i];
    }
    __syncthreads();
    for (int i = tid; i < L_ / 4; i += 64)
        *(float4*)(g_hc + base + i * 4) = ((float4*)sU)[i];
}

// ---------------- y[r] = sum_s hc[s][r] ----------------
__global__ __launch_bounds__(256) void ysum_kernel()
{
    int r = blockIdx.x * blockDim.x + threadIdx.x;
    if (r >= M_) return;
    float acc = 0.f;
    #pragma unroll
    for (int s = 0; s < DS_; s++)
        acc += g_hc[(size_t)s * M_ + r];
    g_y[r] = acc;
}

// ---------------- y_skip = y*silu(gate) + x_conv*D  -> fp16 ----------------
__global__ __launch_bounds__(256) void yskip_kernel(const float* __restrict__ Dp)
{
    int gid = blockIdx.x * blockDim.x + threadIdx.x;
    if (gid >= M_ * (DI_ / 4)) return;
    int iq = gid & (DI_ / 4 - 1);
    int r  = gid >> 9;
    int i  = iq * 4;
    uint2 graw = *(const uint2*)(g_xinner + (size_t)r * N1_ + DI_ + i);
    float2 g0 = __half22float2(*(__half2*)&graw.x);
    float2 g1 = __half22float2(*(__half2*)&graw.y);
    float4 xc = *(const float4*)(g_xconv + (size_t)r * DI_ + i);
    float4 dv = *(const float4*)(Dp + i);
    float yv = g_y[r];
    float f0 = fmaf(yv, g0.x / (1.f + expf(-g0.x)), xc.x * dv.x);
    float f1 = fmaf(yv, g0.y / (1.f + expf(-g0.y)), xc.y * dv.y);
    float f2 = fmaf(yv, g1.x / (1.f + expf(-g1.x)), xc.z * dv.z);
    float f3 = fmaf(yv, g1.y / (1.f + expf(-g1.y)), xc.w * dv.w);
    __half2 a = __floats2half2_rn(f0, f1);
    __half2 b = __floats2half2_rn(f2, f3);
    size_t o = (size_t)r * (DI_ / 4) + iq;
    ((uint2*)g_ys)[o] = make_uint2(*(uint32_t*)&a, *(uint32_t*)&b);
}

// ---------------- launch ----------------
extern "C" void kernel_launch(void* const* d_in, const int* in_sizes, int n_in,
                              void* d_out, int out_size)
{
    const float* x          = (const float*)d_in[0];
    const float* in_proj_w  = (const float*)d_in[1];
    const float* conv_w     = (const float*)d_in[2];
    const float* conv_b     = (const float*)d_in[3];
    const float* A_log      = (const float*)d_in[4];
    const float* Dp         = (const float*)d_in[5];
    const float* delta_w    = (const float*)d_in[6];
    const float* delta_b    = (const float*)d_in[7];
    const float* B_w        = (const float*)d_in[8];
    const float* C_w        = (const float*)d_in[9];
    const float* out_proj_w = (const float*)d_in[10];
    float* out = (float*)d_out;

    __half *p_xinner, *p_xf, *p_w1, *p_wo, *p_ys;
    cudaGetSymbolAddress((void**)&p_xinner, g_xinner);
    cudaGetSymbolAddress((void**)&p_xf, g_xf);
    cudaGetSymbolAddress((void**)&p_w1, g_w1);
    cudaGetSymbolAddress((void**)&p_wo, g_wo);
    cudaGetSymbolAddress((void**)&p_ys, g_ys);

    cudaFuncSetAttribute(gemm_tc<__half>, cudaFuncAttributeMaxDynamicSharedMemorySize, SMEM_TOTAL);
    cudaFuncSetAttribute(gemm_tc<float>,  cudaFuncAttributeMaxDynamicSharedMemorySize, SMEM_TOTAL);

    // 0) convert x and weights to fp16
    cvt_kernel<<<(M_ * DM_ / 4 + 255) / 256, 256>>>(x, p_xf, M_ * DM_ / 4);
    cvt_kernel<<<(N1_ * DM_ / 4 + 255) / 256, 256>>>(in_proj_w, p_w1, N1_ * DM_ / 4);
    cvt_kernel<<<(DM_ * DI_ / 4 + 255) / 256, 256>>>(out_proj_w, p_wo, DM_ * DI_ / 4);

    // 1) x_inner = x @ in_proj_w^T  [8192,4096]  (HMMA fp16, fp16 out)
    gemm_tc<__half><<<dim3(N1_ / BN, M_ / BM), 256, SMEM_TOTAL>>>(
        p_xf, p_w1, p_xinner, M_, N1_, DM_);

    // 2) causal conv + silu (fp16 in, fp32 out)
    conv_silu_kernel<<<(M_ * (DI_ / 4) + 255) / 256, 256>>>(conv_w, conv_b);

    // 3) delta/B/C dots + row sums
    dbc_kernel<<<dim3(M_ / 128, KSPLIT), 256>>>(delta_w, B_w, C_w);

    // 4) scan coefficients (s-major)
    gu_kernel<<<(M_ * DS_ + 255) / 256, 256>>>(A_log, delta_b);

    // 5) parallel scan + reduce over states
    scan2_kernel<<<B_ * DS_, 64>>>();
    ysum_kernel<<<(M_ + 255) / 256, 256>>>();

    // 6) gate + skip fuse -> fp16
    yskip_kernel<<<(M_ * (DI_ / 4) + 255) / 256, 256>>>(Dp);

    // 7) out = y_skip @ out_proj_w^T  [8192,1024]  (HMMA fp16, fp32 out)
    gemm_tc<float><<<dim3(DM_ / BN, M_ / BM), 256, SMEM_TOTAL>>>(
        p_ys, p_wo, out, M_, DM_, DI_);
}

// round 8
// speedup vs baseline: 7.3316x; 1.1505x over previous
#include <cuda_runtime.h>
#include <cuda_fp16.h>
#include <math.h>
#include <stdint.h>

// ---------------- problem dims ----------------
#define B_   4
#define L_   2048
#define DM_  1024
#define DS_  16
#define DC_  4
#define DI_  2048
#define N1_  4096              // 2*DI
#define M_   (B_ * L_)         // 8192
#define NC_  128               // padded N for the dbc GEMM

// ---------------- scratch (__device__ globals, no allocation) ----------------
__device__ __half g_xinner[(size_t)M_ * N1_];    // fp16
__device__ __half g_xc16  [(size_t)M_ * DI_];    // fp16 x_conv
__device__ float g_dots  [(size_t)M_ * NC_];     // delta|B|C|rowsum dots
__device__ float g_G [M_ * DS_];   // s-major: [s][b*L+l]
__device__ float g_U [M_ * DS_];
__device__ float g_Cs[M_ * DS_];
__device__ float g_hc[M_ * DS_];   // h*C, s-major
__device__ float g_y[M_];
__device__ __half g_xf [(size_t)M_  * DM_];
__device__ __half g_w1 [(size_t)N1_ * DM_];
__device__ __half g_wo [(size_t)DM_ * DI_];
__device__ __half g_wc [(size_t)NC_ * DI_];      // [deltaw;Bw;Cw;ones;0...]
__device__ __half g_ys [(size_t)M_  * DI_];

// ---------------- helpers ----------------
__device__ __forceinline__ uint32_t smem_u32(const void* p) {
    uint32_t a;
    asm("{ .reg .u64 t; cvta.to.shared.u64 t, %1; cvt.u32.u64 %0, t; }" : "=r"(a) : "l"(p));
    return a;
}
__device__ __forceinline__ void cp16(uint32_t dst, const void* src) {
    asm volatile("cp.async.cg.shared.global [%0], [%1], 16;" :: "r"(dst), "l"(src));
}
__device__ __forceinline__ void cp_commit() {
    asm volatile("cp.async.commit_group;" ::: "memory");
}
__device__ __forceinline__ void cp_wait1() {
    asm volatile("cp.async.wait_group 1;" ::: "memory");
}
__device__ __forceinline__ void ldm_x4(uint32_t* r, uint32_t addr) {
    asm volatile("ldmatrix.sync.aligned.m8n8.x4.shared.b16 {%0,%1,%2,%3}, [%4];"
        : "=r"(r[0]), "=r"(r[1]), "=r"(r[2]), "=r"(r[3]) : "r"(addr));
}
__device__ __forceinline__ void mma_fp16(float* c, const uint32_t* a, const uint32_t* b) {
    asm volatile(
        "mma.sync.aligned.m16n8k16.row.col.f32.f16.f16.f32 "
        "{%0,%1,%2,%3}, {%4,%5,%6,%7}, {%8,%9}, {%0,%1,%2,%3};"
        : "+f"(c[0]), "+f"(c[1]), "+f"(c[2]), "+f"(c[3])
        : "r"(a[0]), "r"(a[1]), "r"(a[2]), "r"(a[3]), "r"(b[0]), "r"(b[1]));
}

// ---------------- HMMA fp16 GEMM: C[M,N] = A[M,K] @ W[N,K]^T ----------------
// Block 128x128, k-tile 64, 8 warps (2m x 4n), warp tile 64x32.
// 3-stage cp.async pipeline, ONE __syncthreads per k-tile, 2 CTAs/SM.
#define BM 128
#define BN 128
#define BK 64
#define LDS_ROW 72                       // fp16 elems per smem row (64 + 8 pad)
#define TILE_B (128 * LDS_ROW * 2)       // 18432 bytes per 128x64 tile
#define STAGE_B (2 * TILE_B)             // A, W
#define STAGES 3
#define SMEM_TOTAL (STAGES * STAGE_B)    // 110592

__device__ __forceinline__ void stage_load(uint32_t sbase,
    const __half* __restrict__ A, const __half* __restrict__ W,
    int k0, int K, int tid)
{
    const __half* srcs[2] = {A, W};
    #pragma unroll
    for (int a = 0; a < 2; a++) {
        #pragma unroll
        for (int i = 0; i < 4; i++) {
            int idx = i * 256 + tid;        // 0..1023
            int row = idx >> 3;             // 0..127
            int c8  = (idx & 7) * 8;        // 0..56
            const void* g = srcs[a] + (size_t)row * K + k0 + c8;
            uint32_t s = sbase + a * TILE_B + row * (LDS_ROW * 2) + c8 * 2;
            cp16(s, g);
        }
    }
}

template <typename TOut>
__global__ __launch_bounds__(256, 2) void gemm_tc(
    const __half* __restrict__ A, const __half* __restrict__ W,
    TOut* __restrict__ C, int M, int N, int K)
{
    extern __shared__ char smem[];
    uint32_t sb = smem_u32(smem);
    const int tid = threadIdx.x, wid = tid >> 5, lane = tid & 31;
    const int wm = wid >> 2, wn = wid & 3;       // warp 64x32 tile
    const int m0 = blockIdx.y * BM, n0 = blockIdx.x * BN;

    const __half* Ap = A + (size_t)m0 * K;
    const __half* Wp = W + (size_t)n0 * K;

    float acc[4][4][4];
    #pragma unroll
    for (int i = 0; i < 4; i++)
        #pragma unroll
        for (int j = 0; j < 4; j++)
            #pragma unroll
            for (int q = 0; q < 4; q++) acc[i][j][q] = 0.f;

    const int T = K / BK;
    stage_load(sb + 0 * STAGE_B, Ap, Wp, 0, K, tid);
    cp_commit();
    stage_load(sb + 1 * STAGE_B, Ap, Wp, BK, K, tid);
    cp_commit();

    // ldmatrix lane addressing
    const int l15 = lane & 15;
    const int a_khalf = (lane >> 4) & 1;
    const int b_grp = lane >> 3, b_r = lane & 7;
    const int b_row_off = ((b_grp >> 1) << 3) + b_r;
    const int b_kb = (b_grp & 1) * 16;

    for (int t = 0; t < T; t++) {
        cp_wait1();                    // stage t landed (<=1 newer in flight)
        __syncthreads();               // all warps done with slot being reloaded
        if (t + 2 < T)
            stage_load(sb + ((t + 2) % STAGES) * STAGE_B, Ap, Wp,
                       (t + 2) * BK, K, tid);
        cp_commit();                   // uniform commit keeps group count exact

        uint32_t cur = sb + (t % STAGES) * STAGE_B;
        #pragma unroll
        for (int kk = 0; kk < 4; kk++) {
            uint32_t af[4][4], wf[2][4];
            #pragma unroll
            for (int mi = 0; mi < 4; mi++) {
                int row = wm * 64 + mi * 16 + l15;
                uint32_t addr = cur + row * (LDS_ROW * 2) + kk * 32 + a_khalf * 16;
                ldm_x4(af[mi], addr);
            }
            #pragma unroll
            for (int n2 = 0; n2 < 2; n2++) {
                int row = wn * 32 + n2 * 16 + b_row_off;
                uint32_t addr = cur + row * (LDS_ROW * 2) + kk * 32 + b_kb;
                ldm_x4(wf[n2], addr + TILE_B);
            }
            #pragma unroll
            for (int mi = 0; mi < 4; mi++)
                #pragma unroll
                for (int ni = 0; ni < 4; ni++)
                    mma_fp16(acc[mi][ni], af[mi], &wf[ni >> 1][(ni & 1) * 2]);
        }
    }

    const int g = lane >> 2, tq = lane & 3;
    #pragma unroll
    for (int mi = 0; mi < 4; mi++) {
        #pragma unroll
        for (int ni = 0; ni < 4; ni++) {
            int row = m0 + wm * 64 + mi * 16 + g;
            int col = n0 + wn * 32 + ni * 8 + tq * 2;
            if (sizeof(TOut) == 4) {
                *(float2*)((float*)C + (size_t)row * N + col) =
                    make_float2(acc[mi][ni][0], acc[mi][ni][1]);
                *(float2*)((float*)C + (size_t)(row + 8) * N + col) =
                    make_float2(acc[mi][ni][2], acc[mi][ni][3]);
            } else {
                __half2 h0 = __floats2half2_rn(acc[mi][ni][0], acc[mi][ni][1]);
                __half2 h1 = __floats2half2_rn(acc[mi][ni][2], acc[mi][ni][3]);
                *(uint32_t*)((__half*)C + (size_t)row * N + col) = *(uint32_t*)&h0;
                *(uint32_t*)((__half*)C + (size_t)(row + 8) * N + col) = *(uint32_t*)&h1;
            }
        }
    }
}

// ---------------- fp32 -> fp16 convert ----------------
__global__ __launch_bounds__(256) void cvt_kernel(const float* __restrict__ src,
    __half* __restrict__ dst, int n4)
{
    int i = blockIdx.x * blockDim.x + threadIdx.x;
    if (i >= n4) return;
    float4 v = ((const float4*)src)[i];
    __half2 a = __floats2half2_rn(v.x, v.y);
    __half2 b = __floats2half2_rn(v.z, v.w);
    ((uint2*)dst)[i] = make_uint2(*(uint32_t*)&a, *(uint32_t*)&b);
}

// ---------------- build concat weight [deltaw;Bw;Cw;ones;zeros] fp16 -------
__global__ __launch_bounds__(256) void prep_wcat_kernel(
    const float* __restrict__ dw, const float* __restrict__ bw,
    const float* __restrict__ cw)
{
    int i = blockIdx.x * blockDim.x + threadIdx.x;   // over NC_*DI_/4
    if (i >= NC_ * DI_ / 4) return;
    int row = i / (DI_ / 4);
    int c4  = (i % (DI_ / 4)) * 4;
    float4 v;
    if (row < 16)       v = *(const float4*)(dw + (size_t)row * DI_ + c4);
    else if (row < 32)  v = *(const float4*)(bw + (size_t)(row - 16) * DI_ + c4);
    else if (row < 48)  v = *(const float4*)(cw + (size_t)(row - 32) * DI_ + c4);
    else if (row == 48) v = make_float4(1.f, 1.f, 1.f, 1.f);
    else                v = make_float4(0.f, 0.f, 0.f, 0.f);
    __half2 a = __floats2half2_rn(v.x, v.y);
    __half2 b = __floats2half2_rn(v.z, v.w);
    ((uint2*)g_wc)[i] = make_uint2(*(uint32_t*)&a, *(uint32_t*)&b);
}

// ---------------- causal depthwise conv (DC=4) + silu (fp16 in/out) --------
__global__ __launch_bounds__(256) void conv_silu_kernel(
    const float* __restrict__ cw, const float* __restrict__ cb)
{
    int gid = blockIdx.x * blockDim.x + threadIdx.x;
    if (gid >= M_ * (DI_ / 4)) return;
    int iq = gid & (DI_ / 4 - 1);
    int r  = gid >> 9;
    int i  = iq * 4;
    int b  = r >> 11;
    int l  = r & (L_ - 1);

    float4 bias = *(const float4*)(cb + i);
    float acc[4] = {bias.x, bias.y, bias.z, bias.w};
    float w[4][4];
    #pragma unroll
    for (int j = 0; j < 4; j++) {
        float4 t = *(const float4*)(cw + (i + j) * DC_);
        w[j][0] = t.x; w[j][1] = t.y; w[j][2] = t.z; w[j][3] = t.w;
    }
    #pragma unroll
    for (int k = 0; k < DC_; k++) {
        int ls = l + k - (DC_ - 1);
        if (ls >= 0) {
            uint2 raw = *(const uint2*)(g_xinner + (size_t)(b * L_ + ls) * N1_ + i);
            float2 v0 = __half22float2(*(__half2*)&raw.x);
            float2 v1 = __half22float2(*(__half2*)&raw.y);
            acc[0] = fmaf(v0.x, w[0][k], acc[0]);
            acc[1] = fmaf(v0.y, w[1][k], acc[1]);
            acc[2] = fmaf(v1.x, w[2][k], acc[2]);
            acc[3] = fmaf(v1.y, w[3][k], acc[3]);
        }
    }
    float f0 = acc[0] / (1.f + expf(-acc[0]));
    float f1 = acc[1] / (1.f + expf(-acc[1]));
    float f2 = acc[2] / (1.f + expf(-acc[2]));
    float f3 = acc[3] / (1.f + expf(-acc[3]));
    __half2 a = __floats2half2_rn(f0, f1);
    __half2 bb = __floats2half2_rn(f2, f3);
    size_t o = (size_t)r * (DI_ / 4) + iq;
    ((uint2*)g_xc16)[o] = make_uint2(*(uint32_t*)&a, *(uint32_t*)&bb);
}

// ---------------- dots -> scan coefficients (s-major out) ----------------
__global__ __launch_bounds__(256) void gu_kernel(
    const float* __restrict__ A_log, const float* __restrict__ delta_b)
{
    int gid = blockIdx.x * blockDim.x + threadIdx.x;
    if (gid >= M_ * DS_) return;
    int s = gid >> 13;              // gid / M_
    int r = gid & (M_ - 1);
    const float* dp = g_dots + (size_t)r * NC_;
    float dd = dp[s];
    float db = dp[16 + s];
    float dc = dp[32 + s];
    float rs = dp[48];
    float z = dd + delta_b[s];
    float delta = (z > 20.f) ? z : log1pf(expf(z));
    float Aval = -expf(A_log[s]);
    size_t o = (size_t)s * M_ + r;
    g_G[o]  = expf(delta * Aval);
    g_U[o]  = delta * db * (rs * (1.f / (float)DI_));
    g_Cs[o] = dc;
}

// ---------------- parallel scan: one block per (b,s), 64 threads ------------
__global__ __launch_bounds__(64) void scan2_kernel()
{
    __shared__ float sG[L_], sU[L_], sC[L_];
    __shared__ float sA[64], sB[64];
    const int b = blockIdx.x >> 4, s = blockIdx.x & 15;
    const int tid = threadIdx.x;
    const size_t base = (size_t)s * M_ + (size_t)b * L_;

    for (int i = tid; i < L_ / 4; i += 64) {
        ((float4*)sG)[i] = *(const float4*)(g_G  + base + i * 4);
        ((float4*)sU)[i] = *(const float4*)(g_U  + base + i * 4);
        ((float4*)sC)[i] = *(const float4*)(g_Cs + base + i * 4);
    }
    __syncthreads();

    const int CH = L_ / 64;   // 32
    const int l0 = tid * CH;
    float A = 1.f, U = 0.f;
    #pragma unroll
    for (int i = 0; i < CH; i++) {
        float gv = sG[l0 + i];
        A *= gv;
        U = fmaf(gv, U, sU[l0 + i]);
    }
    sA[tid] = A; sB[tid] = U;
    __syncthreads();

    #pragma unroll
    for (int d = 1; d < 64; d <<= 1) {
        float a2 = sA[tid], u2 = sB[tid];
        float a1 = 1.f, u1 = 0.f;
        if (tid >= d) { a1 = sA[tid - d]; u1 = sB[tid - d]; }
        __syncthreads();
        sA[tid] = a2 * a1;
        sB[tid] = fmaf(a2, u1, u2);
        __syncthreads();
    }

    float h = (tid == 0) ? 0.f : sB[tid - 1];
    #pragma unroll
    for (int i = 0; i < CH; i++) {
        h = fmaf(sG[l0 + i], h, sU[l0 + i]);
        sU[l0 + i] = h * sC[l0 + i];
    }
    __syncthreads();
    for (int i = tid; i < L_ / 4; i += 64)
        *(float4*)(g_hc + base + i * 4) = ((float4*)sU)[i];
}

// ---------------- y[r] = sum_s hc[s][r] ----------------
__global__ __launch_bounds__(256) void ysum_kernel()
{
    int r = blockIdx.x * blockDim.x + threadIdx.x;
    if (r >= M_) return;
    float acc = 0.f;
    #pragma unroll
    for (int s = 0; s < DS_; s++)
        acc += g_hc[(size_t)s * M_ + r];
    g_y[r] = acc;
}

// ---------------- y_skip = y*silu(gate) + x_conv*D  -> fp16 ----------------
__global__ __launch_bounds__(256) void yskip_kernel(const float* __restrict__ Dp)
{
    int gid = blockIdx.x * blockDim.x + threadIdx.x;
    if (gid >= M_ * (DI_ / 4)) return;
    int iq = gid & (DI_ / 4 - 1);
    int r  = gid >> 9;
    int i  = iq * 4;
    uint2 graw = *(const uint2*)(g_xinner + (size_t)r * N1_ + DI_ + i);
    float2 g0 = __half22float2(*(__half2*)&graw.x);
    float2 g1 = __half22float2(*(__half2*)&graw.y);
    uint2 xraw = ((const uint2*)g_xc16)[(size_t)r * (DI_ / 4) + iq];
    float2 x0 = __half22float2(*(__half2*)&xraw.x);
    float2 x1 = __half22float2(*(__half2*)&xraw.y);
    float4 dv = *(const float4*)(Dp + i);
    float yv = g_y[r];
    float f0 = fmaf(yv, g0.x / (1.f + expf(-g0.x)), x0.x * dv.x);
    float f1 = fmaf(yv, g0.y / (1.f + expf(-g0.y)), x0.y * dv.y);
    float f2 = fmaf(yv, g1.x / (1.f + expf(-g1.x)), x1.x * dv.z);
    float f3 = fmaf(yv, g1.y / (1.f + expf(-g1.y)), x1.y * dv.w);
    __half2 a = __floats2half2_rn(f0, f1);
    __half2 b = __floats2half2_rn(f2, f3);
    size_t o = (size_t)r * (DI_ / 4) + iq;
    ((uint2*)g_ys)[o] = make_uint2(*(uint32_t*)&a, *(uint32_t*)&b);
}

// ---------------- launch ----------------
extern "C" void kernel_launch(void* const* d_in, const int* in_sizes, int n_in,
                              void* d_out, int out_size)
{
    const float* x          = (const float*)d_in[0];
    const float* in_proj_w  = (const float*)d_in[1];
    const float* conv_w     = (const float*)d_in[2];
    const float* conv_b     = (const float*)d_in[3];
    const float* A_log      = (const float*)d_in[4];
    const float* Dp         = (const float*)d_in[5];
    const float* delta_w    = (const float*)d_in[6];
    const float* delta_b    = (const float*)d_in[7];
    const float* B_w        = (const float*)d_in[8];
    const float* C_w        = (const float*)d_in[9];
    const float* out_proj_w = (const float*)d_in[10];
    float* out = (float*)d_out;

    __half *p_xinner, *p_xf, *p_w1, *p_wo, *p_wc, *p_ys, *p_xc16;
    float *p_dots;
    cudaGetSymbolAddress((void**)&p_xinner, g_xinner);
    cudaGetSymbolAddress((void**)&p_xf, g_xf);
    cudaGetSymbolAddress((void**)&p_w1, g_w1);
    cudaGetSymbolAddress((void**)&p_wo, g_wo);
    cudaGetSymbolAddress((void**)&p_wc, g_wc);
    cudaGetSymbolAddress((void**)&p_ys, g_ys);
    cudaGetSymbolAddress((void**)&p_xc16, g_xc16);
    cudaGetSymbolAddress((void**)&p_dots, g_dots);

    cudaFuncSetAttribute(gemm_tc<__half>, cudaFuncAttributeMaxDynamicSharedMemorySize, SMEM_TOTAL);
    cudaFuncSetAttribute(gemm_tc<float>,  cudaFuncAttributeMaxDynamicSharedMemorySize, SMEM_TOTAL);

    // 0) convert x and weights to fp16; build concat dbc weight
    cvt_kernel<<<(M_ * DM_ / 4 + 255) / 256, 256>>>(x, p_xf, M_ * DM_ / 4);
    cvt_kernel<<<(N1_ * DM_ / 4 + 255) / 256, 256>>>(in_proj_w, p_w1, N1_ * DM_ / 4);
    cvt_kernel<<<(DM_ * DI_ / 4 + 255) / 256, 256>>>(out_proj_w, p_wo, DM_ * DI_ / 4);
    prep_wcat_kernel<<<(NC_ * DI_ / 4 + 255) / 256, 256>>>(delta_w, B_w, C_w);

    // 1) x_inner = x @ in_proj_w^T  [8192,4096]  (HMMA fp16, fp16 out)
    gemm_tc<__half><<<dim3(N1_ / BN, M_ / BM), 256, SMEM_TOTAL>>>(
        p_xf, p_w1, p_xinner, M_, N1_, DM_);

    // 2) causal conv + silu (fp16 in/out)
    conv_silu_kernel<<<(M_ * (DI_ / 4) + 255) / 256, 256>>>(conv_w, conv_b);

    // 3) dots = x_conv @ wcat^T  [8192,128]  (HMMA, includes rowsum col 48)
    gemm_tc<float><<<dim3(1, M_ / BM), 256, SMEM_TOTAL>>>(
        p_xc16, p_wc, p_dots, M_, NC_, DI_);

    // 4) scan coefficients (s-major)
    gu_kernel<<<(M_ * DS_ + 255) / 256, 256>>>(A_log, delta_b);

    // 5) parallel scan + reduce over states
    scan2_kernel<<<B_ * DS_, 64>>>();
    ysum_kernel<<<(M_ + 255) / 256, 256>>>();

    // 6) gate + skip fuse -> fp16
    yskip_kernel<<<(M_ * (DI_ / 4) + 255) / 256, 256>>>(Dp);

    // 7) out = y_skip @ out_proj_w^T  [8192,1024]  (HMMA fp16, fp32 out)
    gemm_tc<float><<<dim3(DM_ / BN, M_ / BM), 256, SMEM_TOTAL>>>(
        p_ys, p_wo, out, M_, DM_, DI_);
}